// round 2
// baseline (speedup 1.0000x reference)
#include <cuda_runtime.h>
#include <cuda_bf16.h>
#include <math.h>

// Problem dims (fixed)
#define BB 2
#define TT 1024
#define RR 2048          // B*T rows
#define EE 256
#define MM 256
#define HH 1024
#define VV 32000
#define WW 8
#define ZK 512           // M+E
#define SK 2048          // W*E

// ---------------- scratch (device globals; no allocation allowed) -------------
__device__ float g_x[RR * EE];          // embedded chars
__device__ float g_drive[RR * MM];      // x @ in_proj
__device__ float g_z[RR * ZK];          // [states | x]
__device__ float g_h[RR * HH];          // hidden (reused lin then loc)
__device__ float g_stacked[RR * SK];    // windowed concat
__device__ float g_loc[(size_t)RR * VV];// loc logits
__device__ float g_gate[RR];

// ---------------- embed: x = emb[chars]; also fill z[:,256:512] ---------------
__global__ void k_embed(const int* __restrict__ chars, const float* __restrict__ emb) {
    int row = blockIdx.x;
    int c = chars[row];
    const float4* src = (const float4*)(emb + (size_t)c * EE);
    float4* dx = (float4*)(g_x + (size_t)row * EE);
    float4* dz = (float4*)(g_z + (size_t)row * ZK + MM);
    int i = threadIdx.x;            // 64 threads * float4 = 256 floats
    float4 v = src[i];
    dx[i] = v;
    dz[i] = v;
}

// ---------------- decay scan: states[t] = d*states[t-1] + drive[t] ------------
__global__ void k_scan(const float* __restrict__ decays) {
    int idx = blockIdx.x * blockDim.x + threadIdx.x;   // 512 threads total
    if (idx >= BB * MM) return;
    int b = idx >> 8;          // /256
    int m = idx & 255;
    float d = decays[m];
    float s = 0.f;
    const float* dr = g_drive + (size_t)b * TT * MM + m;
    float* zs = g_z + (size_t)b * TT * ZK + m;
    for (int t = 0; t < TT; t++) {
        s = fmaf(d, s, dr[(size_t)t * MM]);
        zs[(size_t)t * ZK] = s;
    }
}

// ---------------- stacked[b,t, o*E+e] = x[b, t-o, e] (0 if t<o) ---------------
__global__ void k_stack() {
    int row = blockIdx.x;            // 0..2047
    int o = blockIdx.y;              // 0..7
    int t = row & (TT - 1);
    float4* dst = (float4*)(g_stacked + (size_t)row * SK + o * EE);
    int i = threadIdx.x;             // 64 threads
    if (t - o >= 0) {
        const float4* src = (const float4*)(g_x + (size_t)(row - o) * EE);
        dst[i] = src[i];
    } else {
        dst[i] = make_float4(0.f, 0.f, 0.f, 0.f);
    }
}

// ---------------- SIMT fp32 GEMM: C = act(A[M,K] @ B[K,N] + bias) -------------
// Tiles: 128x128x16, 256 threads, 8x8 per thread. Dims must divide exactly
// (they do for every call here).
#define GBM 128
#define GBN 128
#define GBK 16

template<bool RELU, bool HASBIAS>
__global__ __launch_bounds__(256, 2) void k_gemm(
    const float* __restrict__ A, const float* __restrict__ B,
    const float* __restrict__ bias, float* __restrict__ C,
    int Mdim, int Ndim, int Kdim)
{
    __shared__ float As[GBK][GBM + 4];
    __shared__ float Bs[GBK][GBN + 4];

    int tid = threadIdx.x;
    int m0 = blockIdx.y * GBM;
    int n0 = blockIdx.x * GBN;
    int ty = tid >> 4;      // 0..15 (M sub-tile)
    int tx = tid & 15;      // 0..15 (N sub-tile)

    float acc[8][8];
#pragma unroll
    for (int i = 0; i < 8; i++)
#pragma unroll
        for (int j = 0; j < 8; j++) acc[i][j] = 0.f;

    for (int k0 = 0; k0 < Kdim; k0 += GBK) {
#pragma unroll
        for (int r = 0; r < 2; r++) {
            int idx = tid + r * 256;
            // A tile: 128 rows x 4 float4
            int ar = idx >> 2, ac4 = idx & 3;
            float4 va = *(const float4*)(A + (size_t)(m0 + ar) * Kdim + k0 + ac4 * 4);
            As[ac4 * 4 + 0][ar] = va.x;
            As[ac4 * 4 + 1][ar] = va.y;
            As[ac4 * 4 + 2][ar] = va.z;
            As[ac4 * 4 + 3][ar] = va.w;
            // B tile: 16 rows x 32 float4
            int br = idx >> 5, bc4 = idx & 31;
            float4 vb = *(const float4*)(B + (size_t)(k0 + br) * Ndim + n0 + bc4 * 4);
            *(float4*)&Bs[br][bc4 * 4] = vb;
        }
        __syncthreads();

#pragma unroll
        for (int kk = 0; kk < GBK; kk++) {
            float a[8], b[8];
            *(float4*)&a[0] = *(const float4*)&As[kk][ty * 8];
            *(float4*)&a[4] = *(const float4*)&As[kk][ty * 8 + 4];
            *(float4*)&b[0] = *(const float4*)&Bs[kk][tx * 8];
            *(float4*)&b[4] = *(const float4*)&Bs[kk][tx * 8 + 4];
#pragma unroll
            for (int i = 0; i < 8; i++)
#pragma unroll
                for (int j = 0; j < 8; j++)
                    acc[i][j] = fmaf(a[i], b[j], acc[i][j]);
        }
        __syncthreads();
    }

#pragma unroll
    for (int i = 0; i < 8; i++) {
        int m = m0 + ty * 8 + i;
#pragma unroll
        for (int j = 0; j < 8; j += 4) {
            int n = n0 + tx * 8 + j;
            float4 v;
            v.x = acc[i][j + 0];
            v.y = acc[i][j + 1];
            v.z = acc[i][j + 2];
            v.w = acc[i][j + 3];
            if (HASBIAS) {
                v.x += bias[n + 0];
                v.y += bias[n + 1];
                v.z += bias[n + 2];
                v.w += bias[n + 3];
            }
            if (RELU) {
                v.x = fmaxf(v.x, 0.f);
                v.y = fmaxf(v.y, 0.f);
                v.z = fmaxf(v.z, 0.f);
                v.w = fmaxf(v.w, 0.f);
            }
            *(float4*)(C + (size_t)m * Ndim + n) = v;
        }
    }
}

// ---------------- block reduce (all threads get result) -----------------------
__device__ __forceinline__ float blockReduce(float v, bool domax) {
    __shared__ float sh[8];
    int lane = threadIdx.x & 31;
    int w = threadIdx.x >> 5;
#pragma unroll
    for (int o = 16; o; o >>= 1) {
        float t = __shfl_xor_sync(0xffffffffu, v, o);
        v = domax ? fmaxf(v, t) : (v + t);
    }
    if (lane == 0) sh[w] = v;
    __syncthreads();
    float r = sh[lane & 7];
#pragma unroll
    for (int o = 4; o; o >>= 1) {
        float t = __shfl_xor_sync(0xffffffffu, r, o);
        r = domax ? fmaxf(r, t) : (r + t);
    }
    __syncthreads();
    return r;
}

// ---------------- gate features + sigmoid gate --------------------------------
// one block (256 threads) per row; processes lin (in d_out) and loc logits
__global__ void k_gate(const float* __restrict__ lin,
                       const float* __restrict__ gw,
                       const float* __restrict__ gb)
{
    int row = blockIdx.x;
    float feats[6];
    const float* srcs[2];
    srcs[0] = lin + (size_t)row * VV;
    srcs[1] = g_loc + (size_t)row * VV;

    for (int s = 0; s < 2; s++) {
        const float4* p = (const float4*)srcs[s];
        float mx = -INFINITY, sum = 0.f, sq = 0.f;
        for (int i = threadIdx.x; i < VV / 4; i += 256) {
            float4 v = p[i];
            mx = fmaxf(mx, fmaxf(fmaxf(v.x, v.y), fmaxf(v.z, v.w)));
            sum += (v.x + v.y) + (v.z + v.w);
            sq += v.x * v.x + v.y * v.y + v.z * v.z + v.w * v.w;
        }
        mx  = blockReduce(mx, true);
        sum = blockReduce(sum, false);
        sq  = blockReduce(sq, false);

        float se = 0.f, sl = 0.f;
        for (int i = threadIdx.x; i < VV / 4; i += 256) {
            float4 v = p[i];
            float e;
            e = __expf(v.x - mx); se += e; sl += e * v.x;
            e = __expf(v.y - mx); se += e; sl += e * v.y;
            e = __expf(v.z - mx); se += e; sl += e * v.z;
            e = __expf(v.w - mx); se += e; sl += e * v.w;
        }
        se = blockReduce(se, false);
        sl = blockReduce(sl, false);

        float lse = mx + logf(se);
        float ent = lse - sl / se;
        float mean = sum * (1.f / VV);
        float var = sq * (1.f / VV) - mean * mean;
        feats[s * 3 + 0] = ent;
        feats[s * 3 + 1] = mx;
        feats[s * 3 + 2] = var;
    }

    if (threadIdx.x == 0) {
        float z = gb[0];
#pragma unroll
        for (int i = 0; i < 6; i++) z = fmaf(feats[i], gw[i], z);
        g_gate[row] = 1.f / (1.f + expf(-z));
    }
}

// ---------------- final mix: out = g*lin + (1-g)*loc (in place on d_out) ------
__global__ void k_mix(float* __restrict__ out) {
    const int n4 = RR * (VV / 4);
    for (int i = blockIdx.x * blockDim.x + threadIdx.x; i < n4;
         i += gridDim.x * blockDim.x) {
        int row = i / (VV / 4);
        float g = g_gate[row];
        float4 a = ((const float4*)out)[i];
        float4 c = ((const float4*)g_loc)[i];
        float4 r;
        r.x = fmaf(g, a.x - c.x, c.x);
        r.y = fmaf(g, a.y - c.y, c.y);
        r.z = fmaf(g, a.z - c.z, c.z);
        r.w = fmaf(g, a.w - c.w, c.w);
        ((float4*)out)[i] = r;
    }
}

// ---------------- launcher ----------------------------------------------------
extern "C" void kernel_launch(void* const* d_in, const int* in_sizes, int n_in,
                              void* d_out, int out_size)
{
    const int*   chars   = (const int*)  d_in[0];
    const float* emb     = (const float*)d_in[1];
    const float* in_proj = (const float*)d_in[2];
    const float* decays  = (const float*)d_in[3];
    const float* lin_W1  = (const float*)d_in[4];
    const float* lin_b1  = (const float*)d_in[5];
    const float* lin_W2  = (const float*)d_in[6];
    const float* lin_b2  = (const float*)d_in[7];
    const float* loc_W1  = (const float*)d_in[8];
    const float* loc_b1  = (const float*)d_in[9];
    const float* loc_W2  = (const float*)d_in[10];
    const float* loc_b2  = (const float*)d_in[11];
    const float* gate_W  = (const float*)d_in[12];
    const float* gate_b  = (const float*)d_in[13];
    float* out = (float*)d_out;

    float* px = nullptr, *pdrive = nullptr, *pz = nullptr, *ph = nullptr,
         * pstk = nullptr, *ploc = nullptr;
    cudaGetSymbolAddress((void**)&px,     g_x);
    cudaGetSymbolAddress((void**)&pdrive, g_drive);
    cudaGetSymbolAddress((void**)&pz,     g_z);
    cudaGetSymbolAddress((void**)&ph,     g_h);
    cudaGetSymbolAddress((void**)&pstk,   g_stacked);
    cudaGetSymbolAddress((void**)&ploc,   g_loc);

    // 1) embed (also fills z[:,256:512])
    k_embed<<<RR, 64>>>(chars, emb);

    // 2) drive = x @ in_proj   [2048,256]x[256,256]
    k_gemm<false, false><<<dim3(MM / GBN, RR / GBM), 256>>>(
        px, in_proj, nullptr, pdrive, RR, MM, EE);

    // 3) decay scan -> z[:,0:256]
    k_scan<<<2, 256>>>(decays);

    // 4) windowed stack
    k_stack<<<dim3(RR, WW), 64>>>();

    // 5) lin hidden = relu(z @ lin_W1 + b1)   [2048,512]x[512,1024]
    k_gemm<true, true><<<dim3(HH / GBN, RR / GBM), 256>>>(
        pz, lin_W1, lin_b1, ph, RR, HH, ZK);

    // 6) lin logits -> d_out   [2048,1024]x[1024,32000]
    k_gemm<false, true><<<dim3(VV / GBN, RR / GBM), 256>>>(
        ph, lin_W2, lin_b2, out, RR, VV, HH);

    // 7) loc hidden = relu(stacked @ loc_W1 + b1)   [2048,2048]x[2048,1024]
    k_gemm<true, true><<<dim3(HH / GBN, RR / GBM), 256>>>(
        pstk, loc_W1, loc_b1, ph, RR, HH, SK);

    // 8) loc logits -> g_loc   [2048,1024]x[1024,32000]
    k_gemm<false, true><<<dim3(VV / GBN, RR / GBM), 256>>>(
        ph, loc_W2, loc_b2, ploc, RR, VV, HH);

    // 9) per-row softmax stats + gate
    k_gate<<<RR, 256>>>(out, gate_W, gate_b);

    // 10) mix in place into d_out
    k_mix<<<8192, 256>>>(out);
}

// round 4
// speedup vs baseline: 1.1963x; 1.1963x over previous
#include <cuda_runtime.h>
#include <cuda_bf16.h>
#include <math.h>
#include <stdint.h>

// Problem dims (fixed)
#define BB 2
#define TT 1024
#define RR 2048          // B*T rows
#define EE 256
#define MM 256
#define HH 1024
#define VV 32000
#define WW 8
#define ZK 512           // M+E
#define SK 2048          // W*E

// ================= PTX helpers (arch-agnostic only!) ==========================
__device__ __forceinline__ uint32_t smem_u32(const void* p) {
    uint32_t a;
    asm("{ .reg .u64 t; cvta.to.shared.u64 t, %1; cvt.u32.u64 %0, t; }" : "=r"(a) : "l"(p));
    return a;
}
__device__ __forceinline__ void cp16(uint32_t saddr, const void* g) {
    asm volatile("cp.async.cg.shared.global [%0], [%1], 16;\n" :: "r"(saddr), "l"(g));
}
#define CP_COMMIT() asm volatile("cp.async.commit_group;\n" ::: "memory")
#define CP_WAIT(n)  asm volatile("cp.async.wait_group %0;\n" :: "n"(n) : "memory")

__device__ __forceinline__ void ldmx4(uint32_t* r, uint32_t addr) {
    asm volatile("ldmatrix.sync.aligned.m8n8.x4.shared.b16 {%0,%1,%2,%3}, [%4];"
        : "=r"(r[0]), "=r"(r[1]), "=r"(r[2]), "=r"(r[3]) : "r"(addr));
}
__device__ __forceinline__ void mma16816(float* c, const uint32_t* a,
                                         uint32_t b0, uint32_t b1) {
    asm volatile("mma.sync.aligned.m16n8k16.row.col.f32.bf16.bf16.f32 "
        "{%0,%1,%2,%3}, {%4,%5,%6,%7}, {%8,%9}, {%0,%1,%2,%3};"
        : "+f"(c[0]), "+f"(c[1]), "+f"(c[2]), "+f"(c[3])
        : "r"(a[0]), "r"(a[1]), "r"(a[2]), "r"(a[3]), "r"(b0), "r"(b1));
}

// ---------------- scratch (device globals; no allocation allowed) -------------
__device__ float g_x[RR * EE];
__device__ float g_drive[RR * MM];
__device__ float g_z[RR * ZK];
__device__ float g_h[RR * HH];
__device__ float g_stacked[RR * SK];
__device__ float g_loc[(size_t)RR * VV];
__device__ float g_gate[RR];
// bf16 split buffers
__device__ __nv_bfloat16 g_ah[RR * HH];
__device__ __nv_bfloat16 g_al[RR * HH];
__device__ __nv_bfloat16 g_wl_h[(size_t)VV * HH];   // lin_W2^T hi   [N,K]
__device__ __nv_bfloat16 g_wl_l[(size_t)VV * HH];
__device__ __nv_bfloat16 g_wc_h[(size_t)VV * HH];   // loc_W2^T hi
__device__ __nv_bfloat16 g_wc_l[(size_t)VV * HH];

// ---------------- embed -------------------------------------------------------
__global__ void k_embed(const int* __restrict__ chars, const float* __restrict__ emb) {
    int row = blockIdx.x;
    int c = chars[row];
    const float4* src = (const float4*)(emb + (size_t)c * EE);
    float4* dx = (float4*)(g_x + (size_t)row * EE);
    float4* dz = (float4*)(g_z + (size_t)row * ZK + MM);
    int i = threadIdx.x;
    float4 v = src[i];
    dx[i] = v;
    dz[i] = v;
}

// ---------------- decay scan --------------------------------------------------
__global__ void k_scan(const float* __restrict__ decays) {
    int idx = blockIdx.x * blockDim.x + threadIdx.x;
    if (idx >= BB * MM) return;
    int b = idx >> 8;
    int m = idx & 255;
    float d = decays[m];
    float s = 0.f;
    const float* dr = g_drive + (size_t)b * TT * MM + m;
    float* zs = g_z + (size_t)b * TT * ZK + m;
    for (int t = 0; t < TT; t++) {
        s = fmaf(d, s, dr[(size_t)t * MM]);
        zs[(size_t)t * ZK] = s;
    }
}

// ---------------- windowed stack ----------------------------------------------
__global__ void k_stack() {
    int row = blockIdx.x;
    int o = blockIdx.y;
    int t = row & (TT - 1);
    float4* dst = (float4*)(g_stacked + (size_t)row * SK + o * EE);
    int i = threadIdx.x;
    if (t - o >= 0) {
        const float4* src = (const float4*)(g_x + (size_t)(row - o) * EE);
        dst[i] = src[i];
    } else {
        dst[i] = make_float4(0.f, 0.f, 0.f, 0.f);
    }
}

// ---------------- SIMT fp32 GEMM (small layers) -------------------------------
#define GBM 128
#define GBN 128
#define GBK 16
template<bool RELU, bool HASBIAS>
__global__ __launch_bounds__(256, 2) void k_gemm(
    const float* __restrict__ A, const float* __restrict__ B,
    const float* __restrict__ bias, float* __restrict__ C,
    int Mdim, int Ndim, int Kdim)
{
    __shared__ float As[GBK][GBM + 4];
    __shared__ float Bs[GBK][GBN + 4];
    int tid = threadIdx.x;
    int m0 = blockIdx.y * GBM;
    int n0 = blockIdx.x * GBN;
    int ty = tid >> 4, tx = tid & 15;
    float acc[8][8];
#pragma unroll
    for (int i = 0; i < 8; i++)
#pragma unroll
        for (int j = 0; j < 8; j++) acc[i][j] = 0.f;
    for (int k0 = 0; k0 < Kdim; k0 += GBK) {
#pragma unroll
        for (int r = 0; r < 2; r++) {
            int idx = tid + r * 256;
            int ar = idx >> 2, ac4 = idx & 3;
            float4 va = *(const float4*)(A + (size_t)(m0 + ar) * Kdim + k0 + ac4 * 4);
            As[ac4 * 4 + 0][ar] = va.x;
            As[ac4 * 4 + 1][ar] = va.y;
            As[ac4 * 4 + 2][ar] = va.z;
            As[ac4 * 4 + 3][ar] = va.w;
            int br = idx >> 5, bc4 = idx & 31;
            float4 vb = *(const float4*)(B + (size_t)(k0 + br) * Ndim + n0 + bc4 * 4);
            *(float4*)&Bs[br][bc4 * 4] = vb;
        }
        __syncthreads();
#pragma unroll
        for (int kk = 0; kk < GBK; kk++) {
            float a[8], b[8];
            *(float4*)&a[0] = *(const float4*)&As[kk][ty * 8];
            *(float4*)&a[4] = *(const float4*)&As[kk][ty * 8 + 4];
            *(float4*)&b[0] = *(const float4*)&Bs[kk][tx * 8];
            *(float4*)&b[4] = *(const float4*)&Bs[kk][tx * 8 + 4];
#pragma unroll
            for (int i = 0; i < 8; i++)
#pragma unroll
                for (int j = 0; j < 8; j++)
                    acc[i][j] = fmaf(a[i], b[j], acc[i][j]);
        }
        __syncthreads();
    }
#pragma unroll
    for (int i = 0; i < 8; i++) {
        int m = m0 + ty * 8 + i;
#pragma unroll
        for (int j = 0; j < 8; j += 4) {
            int n = n0 + tx * 8 + j;
            float4 v;
            v.x = acc[i][j + 0]; v.y = acc[i][j + 1];
            v.z = acc[i][j + 2]; v.w = acc[i][j + 3];
            if (HASBIAS) {
                v.x += bias[n + 0]; v.y += bias[n + 1];
                v.z += bias[n + 2]; v.w += bias[n + 3];
            }
            if (RELU) {
                v.x = fmaxf(v.x, 0.f); v.y = fmaxf(v.y, 0.f);
                v.z = fmaxf(v.z, 0.f); v.w = fmaxf(v.w, 0.f);
            }
            *(float4*)(C + (size_t)m * Ndim + n) = v;
        }
    }
}

// ---------------- split fp32 -> bf16 hi/lo (activations) ----------------------
__global__ void k_asplit(const float* __restrict__ A,
                         __nv_bfloat16* __restrict__ Ah,
                         __nv_bfloat16* __restrict__ Al, int n4) {
    int i = blockIdx.x * 256 + threadIdx.x;
    if (i >= n4) return;
    float4 v = ((const float4*)A)[i];
    __nv_bfloat16 h0 = __float2bfloat16(v.x), h1 = __float2bfloat16(v.y);
    __nv_bfloat16 h2 = __float2bfloat16(v.z), h3 = __float2bfloat16(v.w);
    __nv_bfloat16 l0 = __float2bfloat16(v.x - __bfloat162float(h0));
    __nv_bfloat16 l1 = __float2bfloat16(v.y - __bfloat162float(h1));
    __nv_bfloat16 l2 = __float2bfloat16(v.z - __bfloat162float(h2));
    __nv_bfloat16 l3 = __float2bfloat16(v.w - __bfloat162float(h3));
    __nv_bfloat162* ph = (__nv_bfloat162*)Ah;
    __nv_bfloat162* pl = (__nv_bfloat162*)Al;
    ph[2 * i]     = __nv_bfloat162(h0, h1);
    ph[2 * i + 1] = __nv_bfloat162(h2, h3);
    pl[2 * i]     = __nv_bfloat162(l0, l1);
    pl[2 * i + 1] = __nv_bfloat162(l2, l3);
}

// ---------------- transpose + split W[K=1024,N=32000] -> Wt[N,K] hi/lo --------
__global__ void k_wsplitT(const float* __restrict__ Wsrc,
                          __nv_bfloat16* __restrict__ Th,
                          __nv_bfloat16* __restrict__ Tl) {
    __shared__ float tile[32][33];
    int n0 = blockIdx.x * 32;
    int k0 = blockIdx.y * 32;
    int tx = threadIdx.x, ty = threadIdx.y;   // 32 x 8
#pragma unroll
    for (int r = 0; r < 32; r += 8)
        tile[ty + r][tx] = Wsrc[(size_t)(k0 + ty + r) * VV + n0 + tx];
    __syncthreads();
#pragma unroll
    for (int r = 0; r < 32; r += 8) {
        float v = tile[tx][ty + r];
        __nv_bfloat16 h = __float2bfloat16(v);
        __nv_bfloat16 l = __float2bfloat16(v - __bfloat162float(h));
        size_t o = (size_t)(n0 + ty + r) * HH + k0 + tx;
        Th[o] = h;
        Tl[o] = l;
    }
}

// ============ mma.sync bf16 3-product GEMM: C = A[M,K] @ Wt[N,K]^T + bias =====
// CTA tile 128x128, BK=32, 8 warps (warp tile 32x64), cp.async double buffer.
#define MBM 128
#define MBN 128
#define MBK 32
#define MKTOT 1024
#define MNIT (MKTOT / MBK)
#define ROWB 80                       // padded row stride in bytes (40 bf16)
#define MTILE_B (128 * ROWB)          // 10240 bytes per operand tile
#define MSTAGE (4 * MTILE_B)          // Ah, Al, Bh, Bl
#define MSMEM (2 * MSTAGE)            // 81920 B

__global__ __launch_bounds__(256, 1) void k_mma(
    const __nv_bfloat16* __restrict__ Ah, const __nv_bfloat16* __restrict__ Al,
    const __nv_bfloat16* __restrict__ Bh, const __nv_bfloat16* __restrict__ Bl,
    const float* __restrict__ bias, float* __restrict__ C)
{
    extern __shared__ char smem[];
    uint32_t sb = smem_u32(smem);
    int tid = threadIdx.x;
    int w = tid >> 5, lane = tid & 31;
    int wm = w & 3, wn = w >> 2;                // warp tile: rows wm*32, cols wn*64
    int m0 = blockIdx.x * MBM;                  // M fast-varying for L2 reuse of A
    int n0 = blockIdx.y * MBN;

    float acc[2][8][4];
#pragma unroll
    for (int a = 0; a < 2; a++)
#pragma unroll
        for (int b = 0; b < 8; b++)
#pragma unroll
            for (int c = 0; c < 4; c++) acc[a][b][c] = 0.f;

    // loader: 8 cp.async x 16B per thread per stage
    auto load_stage = [&](int s, int k0) {
        uint32_t base = sb + s * MSTAGE;
#pragma unroll
        for (int t = 0; t < 2; t++) {
            int idx = tid + t * 256;            // 0..511
            int r = idx >> 2, c = idx & 3;
            uint32_t so = (uint32_t)(r * ROWB + c * 16);
            size_t ga = (size_t)(m0 + r) * MKTOT + k0 + c * 8;
            cp16(base + so, Ah + ga);
            cp16(base + MTILE_B + so, Al + ga);
            size_t gb = (size_t)(n0 + r) * MKTOT + k0 + c * 8;
            cp16(base + 2 * MTILE_B + so, Bh + gb);
            cp16(base + 3 * MTILE_B + so, Bl + gb);
        }
        CP_COMMIT();
    };

    load_stage(0, 0);

    int lr = lane & 15, lc = lane >> 4;
#pragma unroll 1
    for (int i = 0; i < MNIT; i++) {
        int s = i & 1;
        if (i + 1 < MNIT) { load_stage(s ^ 1, (i + 1) * MBK); CP_WAIT(1); }
        else CP_WAIT(0);
        __syncthreads();

        uint32_t base = sb + s * MSTAGE;
#pragma unroll
        for (int kh = 0; kh < 2; kh++) {
            uint32_t colB = (uint32_t)((kh * 16 + lc * 8) * 2);
            uint32_t ra_h[2][4], ra_l[2][4], rb_h[4][4], rb_l[4][4];
#pragma unroll
            for (int mt = 0; mt < 2; mt++) {
                uint32_t ad = base + (uint32_t)((wm * 32 + mt * 16 + lr) * ROWB) + colB;
                ldmx4(ra_h[mt], ad);
                ldmx4(ra_l[mt], ad + MTILE_B);
            }
#pragma unroll
            for (int np = 0; np < 4; np++) {
                uint32_t bd = base + 2 * MTILE_B +
                              (uint32_t)((wn * 64 + np * 16 + lr) * ROWB) + colB;
                ldmx4(rb_h[np], bd);
                ldmx4(rb_l[np], bd + MTILE_B);
            }
#pragma unroll
            for (int mt = 0; mt < 2; mt++) {
#pragma unroll
                for (int np = 0; np < 4; np++) {
                    mma16816(acc[mt][2 * np],     ra_h[mt], rb_h[np][0], rb_h[np][2]);
                    mma16816(acc[mt][2 * np + 1], ra_h[mt], rb_h[np][1], rb_h[np][3]);
                    mma16816(acc[mt][2 * np],     ra_h[mt], rb_l[np][0], rb_l[np][2]);
                    mma16816(acc[mt][2 * np + 1], ra_h[mt], rb_l[np][1], rb_l[np][3]);
                    mma16816(acc[mt][2 * np],     ra_l[mt], rb_h[np][0], rb_h[np][2]);
                    mma16816(acc[mt][2 * np + 1], ra_l[mt], rb_h[np][1], rb_h[np][3]);
                }
            }
        }
        __syncthreads();
    }

    // epilogue: direct stores with bias
    int qr = lane >> 2, qc = lane & 3;
#pragma unroll
    for (int mt = 0; mt < 2; mt++) {
        int r0 = m0 + wm * 32 + mt * 16 + qr;
#pragma unroll
        for (int nt = 0; nt < 8; nt++) {
            int cidx = n0 + wn * 64 + nt * 8 + qc * 2;
            float b0 = __ldg(bias + cidx), b1 = __ldg(bias + cidx + 1);
            float2 v0 = make_float2(acc[mt][nt][0] + b0, acc[mt][nt][1] + b1);
            float2 v1 = make_float2(acc[mt][nt][2] + b0, acc[mt][nt][3] + b1);
            *(float2*)(C + (size_t)r0 * VV + cidx) = v0;
            *(float2*)(C + (size_t)(r0 + 8) * VV + cidx) = v1;
        }
    }
}

// ---------------- block reduce ------------------------------------------------
__device__ __forceinline__ float blockReduce(float v, bool domax) {
    __shared__ float sh[8];
    int lane = threadIdx.x & 31;
    int wp = threadIdx.x >> 5;
#pragma unroll
    for (int o = 16; o; o >>= 1) {
        float t = __shfl_xor_sync(0xffffffffu, v, o);
        v = domax ? fmaxf(v, t) : (v + t);
    }
    if (lane == 0) sh[wp] = v;
    __syncthreads();
    float r = sh[lane & 7];
#pragma unroll
    for (int o = 4; o; o >>= 1) {
        float t = __shfl_xor_sync(0xffffffffu, r, o);
        r = domax ? fmaxf(r, t) : (r + t);
    }
    __syncthreads();
    return r;
}

// ---------------- gate features + sigmoid gate --------------------------------
__global__ void k_gate(const float* __restrict__ lin,
                       const float* __restrict__ gw,
                       const float* __restrict__ gb)
{
    int row = blockIdx.x;
    float feats[6];
    const float* srcs[2];
    srcs[0] = lin + (size_t)row * VV;
    srcs[1] = g_loc + (size_t)row * VV;
    for (int s = 0; s < 2; s++) {
        const float4* p = (const float4*)srcs[s];
        float mx = -INFINITY, sum = 0.f, sq = 0.f;
        for (int i = threadIdx.x; i < VV / 4; i += 256) {
            float4 v = p[i];
            mx = fmaxf(mx, fmaxf(fmaxf(v.x, v.y), fmaxf(v.z, v.w)));
            sum += (v.x + v.y) + (v.z + v.w);
            sq += v.x * v.x + v.y * v.y + v.z * v.z + v.w * v.w;
        }
        mx  = blockReduce(mx, true);
        sum = blockReduce(sum, false);
        sq  = blockReduce(sq, false);
        float se = 0.f, sl = 0.f;
        for (int i = threadIdx.x; i < VV / 4; i += 256) {
            float4 v = p[i];
            float e;
            e = __expf(v.x - mx); se += e; sl += e * v.x;
            e = __expf(v.y - mx); se += e; sl += e * v.y;
            e = __expf(v.z - mx); se += e; sl += e * v.z;
            e = __expf(v.w - mx); se += e; sl += e * v.w;
        }
        se = blockReduce(se, false);
        sl = blockReduce(sl, false);
        float lse = mx + logf(se);
        float ent = lse - sl / se;
        float mean = sum * (1.f / VV);
        float var = sq * (1.f / VV) - mean * mean;
        feats[s * 3 + 0] = ent;
        feats[s * 3 + 1] = mx;
        feats[s * 3 + 2] = var;
    }
    if (threadIdx.x == 0) {
        float z = gb[0];
#pragma unroll
        for (int i = 0; i < 6; i++) z = fmaf(feats[i], gw[i], z);
        g_gate[row] = 1.f / (1.f + expf(-z));
    }
}

// ---------------- final mix ---------------------------------------------------
__global__ void k_mix(float* __restrict__ out) {
    const int n4 = RR * (VV / 4);
    for (int i = blockIdx.x * blockDim.x + threadIdx.x; i < n4;
         i += gridDim.x * blockDim.x) {
        int row = i / (VV / 4);
        float g = g_gate[row];
        float4 a = ((const float4*)out)[i];
        float4 c = ((const float4*)g_loc)[i];
        float4 r;
        r.x = fmaf(g, a.x - c.x, c.x);
        r.y = fmaf(g, a.y - c.y, c.y);
        r.z = fmaf(g, a.z - c.z, c.z);
        r.w = fmaf(g, a.w - c.w, c.w);
        ((float4*)out)[i] = r;
    }
}

// ---------------- launcher ----------------------------------------------------
extern "C" void kernel_launch(void* const* d_in, const int* in_sizes, int n_in,
                              void* d_out, int out_size)
{
    const int*   chars   = (const int*)  d_in[0];
    const float* emb     = (const float*)d_in[1];
    const float* in_proj = (const float*)d_in[2];
    const float* decays  = (const float*)d_in[3];
    const float* lin_W1  = (const float*)d_in[4];
    const float* lin_b1  = (const float*)d_in[5];
    const float* lin_W2  = (const float*)d_in[6];
    const float* lin_b2  = (const float*)d_in[7];
    const float* loc_W1  = (const float*)d_in[8];
    const float* loc_b1  = (const float*)d_in[9];
    const float* loc_W2  = (const float*)d_in[10];
    const float* loc_b2  = (const float*)d_in[11];
    const float* gate_W  = (const float*)d_in[12];
    const float* gate_b  = (const float*)d_in[13];
    float* out = (float*)d_out;

    float *px, *pdrive, *pz, *ph, *pstk, *ploc;
    __nv_bfloat16 *pah, *pal, *pwlh, *pwll, *pwch, *pwcl;
    cudaGetSymbolAddress((void**)&px,     g_x);
    cudaGetSymbolAddress((void**)&pdrive, g_drive);
    cudaGetSymbolAddress((void**)&pz,     g_z);
    cudaGetSymbolAddress((void**)&ph,     g_h);
    cudaGetSymbolAddress((void**)&pstk,   g_stacked);
    cudaGetSymbolAddress((void**)&ploc,   g_loc);
    cudaGetSymbolAddress((void**)&pah,    g_ah);
    cudaGetSymbolAddress((void**)&pal,    g_al);
    cudaGetSymbolAddress((void**)&pwlh,   g_wl_h);
    cudaGetSymbolAddress((void**)&pwll,   g_wl_l);
    cudaGetSymbolAddress((void**)&pwch,   g_wc_h);
    cudaGetSymbolAddress((void**)&pwcl,   g_wc_l);

    static bool attr_set = false;
    if (!attr_set) {
        cudaFuncSetAttribute(k_mma, cudaFuncAttributeMaxDynamicSharedMemorySize, MSMEM);
        attr_set = true;
    }

    // weight transpose+split (independent, front-loaded)
    k_wsplitT<<<dim3(VV / 32, HH / 32), dim3(32, 8)>>>(lin_W2, pwlh, pwll);
    k_wsplitT<<<dim3(VV / 32, HH / 32), dim3(32, 8)>>>(loc_W2, pwch, pwcl);

    // 1) embed (also fills z[:,256:512])
    k_embed<<<RR, 64>>>(chars, emb);

    // 2) drive = x @ in_proj
    k_gemm<false, false><<<dim3(MM / GBN, RR / GBM), 256>>>(
        px, in_proj, nullptr, pdrive, RR, MM, EE);

    // 3) decay scan
    k_scan<<<2, 256>>>(decays);

    // 4) windowed stack
    k_stack<<<dim3(RR, WW), 64>>>();

    // 5) lin hidden
    k_gemm<true, true><<<dim3(HH / GBN, RR / GBM), 256>>>(
        pz, lin_W1, lin_b1, ph, RR, HH, ZK);

    // 6) split lin hidden, lin logits via mma.sync -> d_out
    k_asplit<<<(RR * HH / 4 + 255) / 256, 256>>>(ph, pah, pal, RR * HH / 4);
    k_mma<<<dim3(RR / MBM, VV / MBN), 256, MSMEM>>>(
        pah, pal, pwlh, pwll, lin_b2, out);

    // 7) loc hidden
    k_gemm<true, true><<<dim3(HH / GBN, RR / GBM), 256>>>(
        pstk, loc_W1, loc_b1, ph, RR, HH, SK);

    // 8) split loc hidden, loc logits via mma.sync -> g_loc
    k_asplit<<<(RR * HH / 4 + 255) / 256, 256>>>(ph, pah, pal, RR * HH / 4);
    k_mma<<<dim3(RR / MBM, VV / MBN), 256, MSMEM>>>(
        pah, pal, pwch, pwcl, loc_b2, ploc);

    // 9) gate + 10) mix
    k_gate<<<RR, 256>>>(out, gate_W, gate_b);
    k_mix<<<8192, 256>>>(out);
}

// round 5
// speedup vs baseline: 1.7823x; 1.4899x over previous
#include <cuda_runtime.h>
#include <cuda_bf16.h>
#include <math.h>
#include <stdint.h>

// Problem dims (fixed)
#define BB 2
#define TT 1024
#define RR 2048          // B*T rows
#define EE 256
#define MM 256
#define HH 1024
#define VV 32000
#define WW 8
#define ZK 512           // M+E
#define SK 2048          // W*E

// ================= PTX helpers (arch-agnostic only!) ==========================
__device__ __forceinline__ uint32_t smem_u32(const void* p) {
    uint32_t a;
    asm("{ .reg .u64 t; cvta.to.shared.u64 t, %1; cvt.u32.u64 %0, t; }" : "=r"(a) : "l"(p));
    return a;
}
__device__ __forceinline__ void cp16(uint32_t saddr, const void* g) {
    asm volatile("cp.async.cg.shared.global [%0], [%1], 16;\n" :: "r"(saddr), "l"(g));
}
#define CP_COMMIT() asm volatile("cp.async.commit_group;\n" ::: "memory")
#define CP_WAIT(n)  asm volatile("cp.async.wait_group %0;\n" :: "n"(n) : "memory")

__device__ __forceinline__ void ldmx4(uint32_t* r, uint32_t addr) {
    asm volatile("ldmatrix.sync.aligned.m8n8.x4.shared.b16 {%0,%1,%2,%3}, [%4];"
        : "=r"(r[0]), "=r"(r[1]), "=r"(r[2]), "=r"(r[3]) : "r"(addr));
}
__device__ __forceinline__ void mma16816(float* c, const uint32_t* a,
                                         uint32_t b0, uint32_t b1) {
    asm volatile("mma.sync.aligned.m16n8k16.row.col.f32.bf16.bf16.f32 "
        "{%0,%1,%2,%3}, {%4,%5,%6,%7}, {%8,%9}, {%0,%1,%2,%3};"
        : "+f"(c[0]), "+f"(c[1]), "+f"(c[2]), "+f"(c[3])
        : "r"(a[0]), "r"(a[1]), "r"(a[2]), "r"(a[3]), "r"(b0), "r"(b1));
}

// ---------------- scratch (device globals; no allocation allowed) -------------
__device__ float g_x[RR * EE];
__device__ float g_drive[RR * MM];
__device__ float g_z[RR * ZK];
__device__ float g_h[RR * HH];
__device__ float g_stacked[RR * SK];
__device__ float g_loc[(size_t)RR * VV];
__device__ float g_gate[RR];
// bf16 split buffers
__device__ __nv_bfloat16 g_ah[RR * HH];
__device__ __nv_bfloat16 g_al[RR * HH];
__device__ __nv_bfloat16 g_wl_h[(size_t)VV * HH];   // lin_W2^T hi   [N,K]
__device__ __nv_bfloat16 g_wl_l[(size_t)VV * HH];
__device__ __nv_bfloat16 g_wc_h[(size_t)VV * HH];   // loc_W2^T hi
__device__ __nv_bfloat16 g_wc_l[(size_t)VV * HH];

// ---------------- embed -------------------------------------------------------
__global__ void k_embed(const int* __restrict__ chars, const float* __restrict__ emb) {
    int row = blockIdx.x;
    int c = chars[row];
    const float4* src = (const float4*)(emb + (size_t)c * EE);
    float4* dx = (float4*)(g_x + (size_t)row * EE);
    float4* dz = (float4*)(g_z + (size_t)row * ZK + MM);
    int i = threadIdx.x;
    float4 v = src[i];
    dx[i] = v;
    dz[i] = v;
}

// ---------------- decay scan --------------------------------------------------
__global__ void k_scan(const float* __restrict__ decays) {
    int idx = blockIdx.x * blockDim.x + threadIdx.x;
    if (idx >= BB * MM) return;
    int b = idx >> 8;
    int m = idx & 255;
    float d = decays[m];
    float s = 0.f;
    const float* dr = g_drive + (size_t)b * TT * MM + m;
    float* zs = g_z + (size_t)b * TT * ZK + m;
    for (int t = 0; t < TT; t++) {
        s = fmaf(d, s, dr[(size_t)t * MM]);
        zs[(size_t)t * ZK] = s;
    }
}

// ---------------- windowed stack ----------------------------------------------
__global__ void k_stack() {
    int row = blockIdx.x;
    int o = blockIdx.y;
    int t = row & (TT - 1);
    float4* dst = (float4*)(g_stacked + (size_t)row * SK + o * EE);
    int i = threadIdx.x;
    if (t - o >= 0) {
        const float4* src = (const float4*)(g_x + (size_t)(row - o) * EE);
        dst[i] = src[i];
    } else {
        dst[i] = make_float4(0.f, 0.f, 0.f, 0.f);
    }
}

// ---------------- SIMT fp32 GEMM (small layers) -------------------------------
#define GBM 128
#define GBN 128
#define GBK 16
template<bool RELU, bool HASBIAS>
__global__ __launch_bounds__(256, 2) void k_gemm(
    const float* __restrict__ A, const float* __restrict__ B,
    const float* __restrict__ bias, float* __restrict__ C,
    int Mdim, int Ndim, int Kdim)
{
    __shared__ float As[GBK][GBM + 4];
    __shared__ float Bs[GBK][GBN + 4];
    int tid = threadIdx.x;
    int m0 = blockIdx.y * GBM;
    int n0 = blockIdx.x * GBN;
    int ty = tid >> 4, tx = tid & 15;
    float acc[8][8];
#pragma unroll
    for (int i = 0; i < 8; i++)
#pragma unroll
        for (int j = 0; j < 8; j++) acc[i][j] = 0.f;
    for (int k0 = 0; k0 < Kdim; k0 += GBK) {
#pragma unroll
        for (int r = 0; r < 2; r++) {
            int idx = tid + r * 256;
            int ar = idx >> 2, ac4 = idx & 3;
            float4 va = *(const float4*)(A + (size_t)(m0 + ar) * Kdim + k0 + ac4 * 4);
            As[ac4 * 4 + 0][ar] = va.x;
            As[ac4 * 4 + 1][ar] = va.y;
            As[ac4 * 4 + 2][ar] = va.z;
            As[ac4 * 4 + 3][ar] = va.w;
            int br = idx >> 5, bc4 = idx & 31;
            float4 vb = *(const float4*)(B + (size_t)(k0 + br) * Ndim + n0 + bc4 * 4);
            *(float4*)&Bs[br][bc4 * 4] = vb;
        }
        __syncthreads();
#pragma unroll
        for (int kk = 0; kk < GBK; kk++) {
            float a[8], b[8];
            *(float4*)&a[0] = *(const float4*)&As[kk][ty * 8];
            *(float4*)&a[4] = *(const float4*)&As[kk][ty * 8 + 4];
            *(float4*)&b[0] = *(const float4*)&Bs[kk][tx * 8];
            *(float4*)&b[4] = *(const float4*)&Bs[kk][tx * 8 + 4];
#pragma unroll
            for (int i = 0; i < 8; i++)
#pragma unroll
                for (int j = 0; j < 8; j++)
                    acc[i][j] = fmaf(a[i], b[j], acc[i][j]);
        }
        __syncthreads();
    }
#pragma unroll
    for (int i = 0; i < 8; i++) {
        int m = m0 + ty * 8 + i;
#pragma unroll
        for (int j = 0; j < 8; j += 4) {
            int n = n0 + tx * 8 + j;
            float4 v;
            v.x = acc[i][j + 0]; v.y = acc[i][j + 1];
            v.z = acc[i][j + 2]; v.w = acc[i][j + 3];
            if (HASBIAS) {
                v.x += bias[n + 0]; v.y += bias[n + 1];
                v.z += bias[n + 2]; v.w += bias[n + 3];
            }
            if (RELU) {
                v.x = fmaxf(v.x, 0.f); v.y = fmaxf(v.y, 0.f);
                v.z = fmaxf(v.z, 0.f); v.w = fmaxf(v.w, 0.f);
            }
            *(float4*)(C + (size_t)m * Ndim + n) = v;
        }
    }
}

// ---------------- split fp32 -> bf16 hi/lo (activations) ----------------------
__global__ void k_asplit(const float* __restrict__ A,
                         __nv_bfloat16* __restrict__ Ah,
                         __nv_bfloat16* __restrict__ Al, int n4) {
    int i = blockIdx.x * 256 + threadIdx.x;
    if (i >= n4) return;
    float4 v = ((const float4*)A)[i];
    __nv_bfloat16 h0 = __float2bfloat16(v.x), h1 = __float2bfloat16(v.y);
    __nv_bfloat16 h2 = __float2bfloat16(v.z), h3 = __float2bfloat16(v.w);
    __nv_bfloat16 l0 = __float2bfloat16(v.x - __bfloat162float(h0));
    __nv_bfloat16 l1 = __float2bfloat16(v.y - __bfloat162float(h1));
    __nv_bfloat16 l2 = __float2bfloat16(v.z - __bfloat162float(h2));
    __nv_bfloat16 l3 = __float2bfloat16(v.w - __bfloat162float(h3));
    __nv_bfloat162* ph = (__nv_bfloat162*)Ah;
    __nv_bfloat162* pl = (__nv_bfloat162*)Al;
    ph[2 * i]     = __nv_bfloat162(h0, h1);
    ph[2 * i + 1] = __nv_bfloat162(h2, h3);
    pl[2 * i]     = __nv_bfloat162(l0, l1);
    pl[2 * i + 1] = __nv_bfloat162(l2, l3);
}

// ---------------- transpose + split W[K=1024,N=32000] -> Wt[N,K] hi/lo --------
__global__ void k_wsplitT(const float* __restrict__ Wsrc,
                          __nv_bfloat16* __restrict__ Th,
                          __nv_bfloat16* __restrict__ Tl) {
    __shared__ float tile[32][33];
    int n0 = blockIdx.x * 32;
    int k0 = blockIdx.y * 32;
    int tx = threadIdx.x, ty = threadIdx.y;   // 32 x 8
#pragma unroll
    for (int r = 0; r < 32; r += 8)
        tile[ty + r][tx] = Wsrc[(size_t)(k0 + ty + r) * VV + n0 + tx];
    __syncthreads();
#pragma unroll
    for (int r = 0; r < 32; r += 8) {
        float v = tile[tx][ty + r];
        __nv_bfloat16 h = __float2bfloat16(v);
        __nv_bfloat16 l = __float2bfloat16(v - __bfloat162float(h));
        size_t o = (size_t)(n0 + ty + r) * HH + k0 + tx;
        Th[o] = h;
        Tl[o] = l;
    }
}

// ============ mma.sync bf16 3-product GEMM: C = A[M,K] @ Wt[N,K]^T + bias =====
// CTA tile 128x128, BK=32, 8 warps (warp tile 32x64), cp.async double buffer.
// MMA schedule: three product passes (hh, hl, lh) so each accumulator quad is
// touched once per pass -> 16 independent chains per warp hide HMMA latency.
#define MBM 128
#define MBN 128
#define MBK 32
#define MKTOT 1024
#define MNIT (MKTOT / MBK)
#define ROWB 80                       // padded row stride in bytes (40 bf16)
#define MTILE_B (128 * ROWB)          // 10240 bytes per operand tile
#define MSTAGE (4 * MTILE_B)          // Ah, Al, Bh, Bl
#define MSMEM (2 * MSTAGE)            // 81920 B

__global__ __launch_bounds__(256, 1) void k_mma(
    const __nv_bfloat16* __restrict__ Ah, const __nv_bfloat16* __restrict__ Al,
    const __nv_bfloat16* __restrict__ Bh, const __nv_bfloat16* __restrict__ Bl,
    const float* __restrict__ bias, float* __restrict__ C)
{
    extern __shared__ char smem[];
    uint32_t sb = smem_u32(smem);
    int tid = threadIdx.x;
    int w = tid >> 5, lane = tid & 31;
    int wm = w & 3, wn = w >> 2;                // warp tile: rows wm*32, cols wn*64
    int m0 = blockIdx.x * MBM;                  // M fast-varying for L2 reuse
    int n0 = blockIdx.y * MBN;

    float acc[2][8][4];
#pragma unroll
    for (int a = 0; a < 2; a++)
#pragma unroll
        for (int b = 0; b < 8; b++)
#pragma unroll
            for (int c = 0; c < 4; c++) acc[a][b][c] = 0.f;

    // loader: 8 cp.async x 16B per thread per stage
    auto load_stage = [&](int s, int k0) {
        uint32_t base = sb + s * MSTAGE;
#pragma unroll
        for (int t = 0; t < 2; t++) {
            int idx = tid + t * 256;            // 0..511
            int r = idx >> 2, c = idx & 3;
            uint32_t so = (uint32_t)(r * ROWB + c * 16);
            size_t ga = (size_t)(m0 + r) * MKTOT + k0 + c * 8;
            cp16(base + so, Ah + ga);
            cp16(base + MTILE_B + so, Al + ga);
            size_t gb = (size_t)(n0 + r) * MKTOT + k0 + c * 8;
            cp16(base + 2 * MTILE_B + so, Bh + gb);
            cp16(base + 3 * MTILE_B + so, Bl + gb);
        }
        CP_COMMIT();
    };

    load_stage(0, 0);

    int lr = lane & 15, lc = lane >> 4;
#pragma unroll 1
    for (int i = 0; i < MNIT; i++) {
        int s = i & 1;
        if (i + 1 < MNIT) { load_stage(s ^ 1, (i + 1) * MBK); CP_WAIT(1); }
        else CP_WAIT(0);
        __syncthreads();

        uint32_t base = sb + s * MSTAGE;
#pragma unroll
        for (int kh = 0; kh < 2; kh++) {
            uint32_t colB = (uint32_t)((kh * 16 + lc * 8) * 2);
            uint32_t ra_h[2][4], ra_l[2][4], rb_h[4][4], rb_l[4][4];
#pragma unroll
            for (int mt = 0; mt < 2; mt++) {
                uint32_t ad = base + (uint32_t)((wm * 32 + mt * 16 + lr) * ROWB) + colB;
                ldmx4(ra_h[mt], ad);
                ldmx4(ra_l[mt], ad + MTILE_B);
            }
#pragma unroll
            for (int np = 0; np < 4; np++) {
                uint32_t bd = base + 2 * MTILE_B +
                              (uint32_t)((wn * 64 + np * 16 + lr) * ROWB) + colB;
                ldmx4(rb_h[np], bd);
                ldmx4(rb_l[np], bd + MTILE_B);
            }
            // pass 1: hi*hi — all 16 accumulator quads touched once
#pragma unroll
            for (int mt = 0; mt < 2; mt++)
#pragma unroll
                for (int np = 0; np < 4; np++) {
                    mma16816(acc[mt][2 * np],     ra_h[mt], rb_h[np][0], rb_h[np][2]);
                    mma16816(acc[mt][2 * np + 1], ra_h[mt], rb_h[np][1], rb_h[np][3]);
                }
            // pass 2: hi*lo
#pragma unroll
            for (int mt = 0; mt < 2; mt++)
#pragma unroll
                for (int np = 0; np < 4; np++) {
                    mma16816(acc[mt][2 * np],     ra_h[mt], rb_l[np][0], rb_l[np][2]);
                    mma16816(acc[mt][2 * np + 1], ra_h[mt], rb_l[np][1], rb_l[np][3]);
                }
            // pass 3: lo*hi
#pragma unroll
            for (int mt = 0; mt < 2; mt++)
#pragma unroll
                for (int np = 0; np < 4; np++) {
                    mma16816(acc[mt][2 * np],     ra_l[mt], rb_h[np][0], rb_h[np][2]);
                    mma16816(acc[mt][2 * np + 1], ra_l[mt], rb_h[np][1], rb_h[np][3]);
                }
        }
        __syncthreads();
    }

    // epilogue: direct stores with bias
    int qr = lane >> 2, qc = lane & 3;
#pragma unroll
    for (int mt = 0; mt < 2; mt++) {
        int r0 = m0 + wm * 32 + mt * 16 + qr;
#pragma unroll
        for (int nt = 0; nt < 8; nt++) {
            int cidx = n0 + wn * 64 + nt * 8 + qc * 2;
            float b0 = __ldg(bias + cidx), b1 = __ldg(bias + cidx + 1);
            float2 v0 = make_float2(acc[mt][nt][0] + b0, acc[mt][nt][1] + b1);
            float2 v1 = make_float2(acc[mt][nt][2] + b0, acc[mt][nt][3] + b1);
            *(float2*)(C + (size_t)r0 * VV + cidx) = v0;
            *(float2*)(C + (size_t)(r0 + 8) * VV + cidx) = v1;
        }
    }
}

// ---------------- block reduce ------------------------------------------------
__device__ __forceinline__ float blockReduce(float v, bool domax) {
    __shared__ float sh[8];
    int lane = threadIdx.x & 31;
    int wp = threadIdx.x >> 5;
#pragma unroll
    for (int o = 16; o; o >>= 1) {
        float t = __shfl_xor_sync(0xffffffffu, v, o);
        v = domax ? fmaxf(v, t) : (v + t);
    }
    if (lane == 0) sh[wp] = v;
    __syncthreads();
    float r = sh[lane & 7];
#pragma unroll
    for (int o = 4; o; o >>= 1) {
        float t = __shfl_xor_sync(0xffffffffu, r, o);
        r = domax ? fmaxf(r, t) : (r + t);
    }
    __syncthreads();
    return r;
}

// ---------------- gate features + sigmoid gate --------------------------------
__global__ void k_gate(const float* __restrict__ lin,
                       const float* __restrict__ gw,
                       const float* __restrict__ gb)
{
    int row = blockIdx.x;
    float feats[6];
    const float* srcs[2];
    srcs[0] = lin + (size_t)row * VV;
    srcs[1] = g_loc + (size_t)row * VV;
    for (int s = 0; s < 2; s++) {
        const float4* p = (const float4*)srcs[s];
        float mx = -INFINITY, sum = 0.f, sq = 0.f;
        for (int i = threadIdx.x; i < VV / 4; i += 256) {
            float4 v = p[i];
            mx = fmaxf(mx, fmaxf(fmaxf(v.x, v.y), fmaxf(v.z, v.w)));
            sum += (v.x + v.y) + (v.z + v.w);
            sq += v.x * v.x + v.y * v.y + v.z * v.z + v.w * v.w;
        }
        mx  = blockReduce(mx, true);
        sum = blockReduce(sum, false);
        sq  = blockReduce(sq, false);
        float se = 0.f, sl = 0.f;
        for (int i = threadIdx.x; i < VV / 4; i += 256) {
            float4 v = p[i];
            float e;
            e = __expf(v.x - mx); se += e; sl += e * v.x;
            e = __expf(v.y - mx); se += e; sl += e * v.y;
            e = __expf(v.z - mx); se += e; sl += e * v.z;
            e = __expf(v.w - mx); se += e; sl += e * v.w;
        }
        se = blockReduce(se, false);
        sl = blockReduce(sl, false);
        float lse = mx + logf(se);
        float ent = lse - sl / se;
        float mean = sum * (1.f / VV);
        float var = sq * (1.f / VV) - mean * mean;
        feats[s * 3 + 0] = ent;
        feats[s * 3 + 1] = mx;
        feats[s * 3 + 2] = var;
    }
    if (threadIdx.x == 0) {
        float z = gb[0];
#pragma unroll
        for (int i = 0; i < 6; i++) z = fmaf(feats[i], gw[i], z);
        g_gate[row] = 1.f / (1.f + expf(-z));
    }
}

// ---------------- final mix ---------------------------------------------------
__global__ void k_mix(float* __restrict__ out) {
    const int n4 = RR * (VV / 4);
    for (int i = blockIdx.x * blockDim.x + threadIdx.x; i < n4;
         i += gridDim.x * blockDim.x) {
        int row = i / (VV / 4);
        float g = g_gate[row];
        float4 a = ((const float4*)out)[i];
        float4 c = ((const float4*)g_loc)[i];
        float4 r;
        r.x = fmaf(g, a.x - c.x, c.x);
        r.y = fmaf(g, a.y - c.y, c.y);
        r.z = fmaf(g, a.z - c.z, c.z);
        r.w = fmaf(g, a.w - c.w, c.w);
        ((float4*)out)[i] = r;
    }
}

// ---------------- launcher ----------------------------------------------------
extern "C" void kernel_launch(void* const* d_in, const int* in_sizes, int n_in,
                              void* d_out, int out_size)
{
    const int*   chars   = (const int*)  d_in[0];
    const float* emb     = (const float*)d_in[1];
    const float* in_proj = (const float*)d_in[2];
    const float* decays  = (const float*)d_in[3];
    const float* lin_W1  = (const float*)d_in[4];
    const float* lin_b1  = (const float*)d_in[5];
    const float* lin_W2  = (const float*)d_in[6];
    const float* lin_b2  = (const float*)d_in[7];
    const float* loc_W1  = (const float*)d_in[8];
    const float* loc_b1  = (const float*)d_in[9];
    const float* loc_W2  = (const float*)d_in[10];
    const float* loc_b2  = (const float*)d_in[11];
    const float* gate_W  = (const float*)d_in[12];
    const float* gate_b  = (const float*)d_in[13];
    float* out = (float*)d_out;

    float *px, *pdrive, *pz, *ph, *pstk, *ploc;
    __nv_bfloat16 *pah, *pal, *pwlh, *pwll, *pwch, *pwcl;
    cudaGetSymbolAddress((void**)&px,     g_x);
    cudaGetSymbolAddress((void**)&pdrive, g_drive);
    cudaGetSymbolAddress((void**)&pz,     g_z);
    cudaGetSymbolAddress((void**)&ph,     g_h);
    cudaGetSymbolAddress((void**)&pstk,   g_stacked);
    cudaGetSymbolAddress((void**)&ploc,   g_loc);
    cudaGetSymbolAddress((void**)&pah,    g_ah);
    cudaGetSymbolAddress((void**)&pal,    g_al);
    cudaGetSymbolAddress((void**)&pwlh,   g_wl_h);
    cudaGetSymbolAddress((void**)&pwll,   g_wl_l);
    cudaGetSymbolAddress((void**)&pwch,   g_wc_h);
    cudaGetSymbolAddress((void**)&pwcl,   g_wc_l);

    static bool attr_set = false;
    if (!attr_set) {
        cudaFuncSetAttribute(k_mma, cudaFuncAttributeMaxDynamicSharedMemorySize, MSMEM);
        attr_set = true;
    }

    // weight transpose+split (independent, front-loaded)
    k_wsplitT<<<dim3(VV / 32, HH / 32), dim3(32, 8)>>>(lin_W2, pwlh, pwll);
    k_wsplitT<<<dim3(VV / 32, HH / 32), dim3(32, 8)>>>(loc_W2, pwch, pwcl);

    // 1) embed (also fills z[:,256:512])
    k_embed<<<RR, 64>>>(chars, emb);

    // 2) drive = x @ in_proj
    k_gemm<false, false><<<dim3(MM / GBN, RR / GBM), 256>>>(
        px, in_proj, nullptr, pdrive, RR, MM, EE);

    // 3) decay scan
    k_scan<<<2, 256>>>(decays);

    // 4) windowed stack
    k_stack<<<dim3(RR, WW), 64>>>();

    // 5) lin hidden
    k_gemm<true, true><<<dim3(HH / GBN, RR / GBM), 256>>>(
        pz, lin_W1, lin_b1, ph, RR, HH, ZK);

    // 6) split lin hidden, lin logits via mma.sync -> d_out
    k_asplit<<<(RR * HH / 4 + 255) / 256, 256>>>(ph, pah, pal, RR * HH / 4);
    k_mma<<<dim3(RR / MBM, VV / MBN), 256, MSMEM>>>(
        pah, pal, pwlh, pwll, lin_b2, out);

    // 7) loc hidden
    k_gemm<true, true><<<dim3(HH / GBN, RR / GBM), 256>>>(
        pstk, loc_W1, loc_b1, ph, RR, HH, SK);

    // 8) split loc hidden, loc logits via mma.sync -> g_loc
    k_asplit<<<(RR * HH / 4 + 255) / 256, 256>>>(ph, pah, pal, RR * HH / 4);
    k_mma<<<dim3(RR / MBM, VV / MBN), 256, MSMEM>>>(
        pah, pal, pwch, pwcl, loc_b2, ploc);

    // 9) gate + 10) mix
    k_gate<<<RR, 256>>>(out, gate_W, gate_b);
    k_mix<<<8192, 256>>>(out);
}

// round 6
// speedup vs baseline: 1.8856x; 1.0580x over previous
#include <cuda_runtime.h>
#include <cuda_bf16.h>
#include <math.h>
#include <stdint.h>

// Problem dims (fixed)
#define BB 2
#define TT 1024
#define RR 2048          // B*T rows
#define EE 256
#define MM 256
#define HH 1024
#define VV 32000
#define WW 8
#define ZK 512           // M+E
#define SK 2048          // W*E

// ================= PTX helpers (arch-agnostic only!) ==========================
__device__ __forceinline__ uint32_t smem_u32(const void* p) {
    uint32_t a;
    asm("{ .reg .u64 t; cvta.to.shared.u64 t, %1; cvt.u32.u64 %0, t; }" : "=r"(a) : "l"(p));
    return a;
}
__device__ __forceinline__ void cp16(uint32_t saddr, const void* g) {
    asm volatile("cp.async.cg.shared.global [%0], [%1], 16;\n" :: "r"(saddr), "l"(g));
}
#define CP_COMMIT() asm volatile("cp.async.commit_group;\n" ::: "memory")
#define CP_WAIT(n)  asm volatile("cp.async.wait_group %0;\n" :: "n"(n) : "memory")

__device__ __forceinline__ void ldmx4(uint32_t* r, uint32_t addr) {
    asm volatile("ldmatrix.sync.aligned.m8n8.x4.shared.b16 {%0,%1,%2,%3}, [%4];"
        : "=r"(r[0]), "=r"(r[1]), "=r"(r[2]), "=r"(r[3]) : "r"(addr));
}
__device__ __forceinline__ void mma16816(float* c, const uint32_t* a,
                                         uint32_t b0, uint32_t b1) {
    asm volatile("mma.sync.aligned.m16n8k16.row.col.f32.bf16.bf16.f32 "
        "{%0,%1,%2,%3}, {%4,%5,%6,%7}, {%8,%9}, {%0,%1,%2,%3};"
        : "+f"(c[0]), "+f"(c[1]), "+f"(c[2]), "+f"(c[3])
        : "r"(a[0]), "r"(a[1]), "r"(a[2]), "r"(a[3]), "r"(b0), "r"(b1));
}

// ---------------- scratch (device globals; no allocation allowed) -------------
__device__ float g_x[RR * EE];
__device__ float g_drive[RR * MM];
__device__ float g_z[RR * ZK];
__device__ float g_h[RR * HH];
__device__ float g_stacked[RR * SK];
__device__ float g_loc[(size_t)RR * VV];
// bf16 split buffers
__device__ __nv_bfloat16 g_ah[RR * HH];
__device__ __nv_bfloat16 g_al[RR * HH];
__device__ __nv_bfloat16 g_zh[RR * ZK];
__device__ __nv_bfloat16 g_zl[RR * ZK];
__device__ __nv_bfloat16 g_sh[RR * SK];
__device__ __nv_bfloat16 g_sl[RR * SK];
__device__ __nv_bfloat16 g_wl_h[(size_t)VV * HH];   // lin_W2^T hi [N,K]
__device__ __nv_bfloat16 g_wl_l[(size_t)VV * HH];
__device__ __nv_bfloat16 g_wc_h[(size_t)VV * HH];   // loc_W2^T hi
__device__ __nv_bfloat16 g_wc_l[(size_t)VV * HH];
__device__ __nv_bfloat16 g_w1l_h[HH * ZK];          // lin_W1^T hi [H,ZK]
__device__ __nv_bfloat16 g_w1l_l[HH * ZK];
__device__ __nv_bfloat16 g_w1c_h[(size_t)HH * SK];  // loc_W1^T hi [H,SK]
__device__ __nv_bfloat16 g_w1c_l[(size_t)HH * SK];

// ---------------- embed -------------------------------------------------------
__global__ void k_embed(const int* __restrict__ chars, const float* __restrict__ emb) {
    int row = blockIdx.x;
    int c = chars[row];
    const float4* src = (const float4*)(emb + (size_t)c * EE);
    float4* dx = (float4*)(g_x + (size_t)row * EE);
    float4* dz = (float4*)(g_z + (size_t)row * ZK + MM);
    int i = threadIdx.x;
    float4 v = src[i];
    dx[i] = v;
    dz[i] = v;
}

// ---------------- decay scan --------------------------------------------------
__global__ void k_scan(const float* __restrict__ decays) {
    int idx = blockIdx.x * blockDim.x + threadIdx.x;
    if (idx >= BB * MM) return;
    int b = idx >> 8;
    int m = idx & 255;
    float d = decays[m];
    float s = 0.f;
    const float* dr = g_drive + (size_t)b * TT * MM + m;
    float* zs = g_z + (size_t)b * TT * ZK + m;
    for (int t = 0; t < TT; t++) {
        s = fmaf(d, s, dr[(size_t)t * MM]);
        zs[(size_t)t * ZK] = s;
    }
}

// ---------------- windowed stack ----------------------------------------------
__global__ void k_stack() {
    int row = blockIdx.x;
    int o = blockIdx.y;
    int t = row & (TT - 1);
    float4* dst = (float4*)(g_stacked + (size_t)row * SK + o * EE);
    int i = threadIdx.x;
    if (t - o >= 0) {
        const float4* src = (const float4*)(g_x + (size_t)(row - o) * EE);
        dst[i] = src[i];
    } else {
        dst[i] = make_float4(0.f, 0.f, 0.f, 0.f);
    }
}

// ---------------- SIMT fp32 GEMM (drive only) ---------------------------------
#define GBM 128
#define GBN 128
#define GBK 16
__global__ __launch_bounds__(256, 2) void k_gemm(
    const float* __restrict__ A, const float* __restrict__ B,
    float* __restrict__ C, int Ndim, int Kdim)
{
    __shared__ float As[GBK][GBM + 4];
    __shared__ float Bs[GBK][GBN + 4];
    int tid = threadIdx.x;
    int m0 = blockIdx.y * GBM;
    int n0 = blockIdx.x * GBN;
    int ty = tid >> 4, tx = tid & 15;
    float acc[8][8];
#pragma unroll
    for (int i = 0; i < 8; i++)
#pragma unroll
        for (int j = 0; j < 8; j++) acc[i][j] = 0.f;
    for (int k0 = 0; k0 < Kdim; k0 += GBK) {
#pragma unroll
        for (int r = 0; r < 2; r++) {
            int idx = tid + r * 256;
            int ar = idx >> 2, ac4 = idx & 3;
            float4 va = *(const float4*)(A + (size_t)(m0 + ar) * Kdim + k0 + ac4 * 4);
            As[ac4 * 4 + 0][ar] = va.x;
            As[ac4 * 4 + 1][ar] = va.y;
            As[ac4 * 4 + 2][ar] = va.z;
            As[ac4 * 4 + 3][ar] = va.w;
            int br = idx >> 5, bc4 = idx & 31;
            float4 vb = *(const float4*)(B + (size_t)(k0 + br) * Ndim + n0 + bc4 * 4);
            *(float4*)&Bs[br][bc4 * 4] = vb;
        }
        __syncthreads();
#pragma unroll
        for (int kk = 0; kk < GBK; kk++) {
            float a[8], b[8];
            *(float4*)&a[0] = *(const float4*)&As[kk][ty * 8];
            *(float4*)&a[4] = *(const float4*)&As[kk][ty * 8 + 4];
            *(float4*)&b[0] = *(const float4*)&Bs[kk][tx * 8];
            *(float4*)&b[4] = *(const float4*)&Bs[kk][tx * 8 + 4];
#pragma unroll
            for (int i = 0; i < 8; i++)
#pragma unroll
                for (int j = 0; j < 8; j++)
                    acc[i][j] = fmaf(a[i], b[j], acc[i][j]);
        }
        __syncthreads();
    }
#pragma unroll
    for (int i = 0; i < 8; i++) {
        int m = m0 + ty * 8 + i;
#pragma unroll
        for (int j = 0; j < 8; j += 4) {
            int n = n0 + tx * 8 + j;
            float4 v;
            v.x = acc[i][j + 0]; v.y = acc[i][j + 1];
            v.z = acc[i][j + 2]; v.w = acc[i][j + 3];
            *(float4*)(C + (size_t)m * Ndim + n) = v;
        }
    }
}

// ---------------- split fp32 -> bf16 hi/lo (activations) ----------------------
__global__ void k_asplit(const float* __restrict__ A,
                         __nv_bfloat16* __restrict__ Ah,
                         __nv_bfloat16* __restrict__ Al, int n4) {
    int i = blockIdx.x * 256 + threadIdx.x;
    if (i >= n4) return;
    float4 v = ((const float4*)A)[i];
    __nv_bfloat16 h0 = __float2bfloat16(v.x), h1 = __float2bfloat16(v.y);
    __nv_bfloat16 h2 = __float2bfloat16(v.z), h3 = __float2bfloat16(v.w);
    __nv_bfloat16 l0 = __float2bfloat16(v.x - __bfloat162float(h0));
    __nv_bfloat16 l1 = __float2bfloat16(v.y - __bfloat162float(h1));
    __nv_bfloat16 l2 = __float2bfloat16(v.z - __bfloat162float(h2));
    __nv_bfloat16 l3 = __float2bfloat16(v.w - __bfloat162float(h3));
    __nv_bfloat162* ph = (__nv_bfloat162*)Ah;
    __nv_bfloat162* pl = (__nv_bfloat162*)Al;
    ph[2 * i]     = __nv_bfloat162(h0, h1);
    ph[2 * i + 1] = __nv_bfloat162(h2, h3);
    pl[2 * i]     = __nv_bfloat162(l0, l1);
    pl[2 * i + 1] = __nv_bfloat162(l2, l3);
}

// ---------- transpose + split W[Krows, Ncols] -> Wt[N,K] hi/lo ----------------
__global__ void k_wsplitT(const float* __restrict__ Wsrc,
                          __nv_bfloat16* __restrict__ Th,
                          __nv_bfloat16* __restrict__ Tl,
                          int Krows, int Ncols) {
    __shared__ float tile[32][33];
    int n0 = blockIdx.x * 32;
    int k0 = blockIdx.y * 32;
    int tx = threadIdx.x, ty = threadIdx.y;   // 32 x 8
#pragma unroll
    for (int r = 0; r < 32; r += 8)
        tile[ty + r][tx] = Wsrc[(size_t)(k0 + ty + r) * Ncols + n0 + tx];
    __syncthreads();
#pragma unroll
    for (int r = 0; r < 32; r += 8) {
        float v = tile[tx][ty + r];
        __nv_bfloat16 h = __float2bfloat16(v);
        __nv_bfloat16 l = __float2bfloat16(v - __bfloat162float(h));
        size_t o = (size_t)(n0 + ty + r) * Krows + k0 + tx;
        Th[o] = h;
        Tl[o] = l;
    }
}

// ====== split-bf16 mma.sync GEMM: C[M,N] = A[M,K] @ Wt[N,K]^T + bias ==========
// CTA tile 128x256, BK=32, 8 warps (64x64 warp tiles), 3-stage cp.async.
#define MBM2 128
#define MBN2 256
#define MBK2 32
#define ROW2 80                          // padded row stride bytes (40 bf16)
#define ST_A (128 * ROW2)                // 10240
#define ST_B (256 * ROW2)                // 20480
#define STG2 (2 * ST_A + 2 * ST_B)       // 61440
#define NSTG 3
#define MSMEM2 (NSTG * STG2)             // 184320

template<bool RELU>
__global__ __launch_bounds__(256, 1) void k_mma2(
    const __nv_bfloat16* __restrict__ Ah, const __nv_bfloat16* __restrict__ Al,
    const __nv_bfloat16* __restrict__ Bh, const __nv_bfloat16* __restrict__ Bl,
    const float* __restrict__ bias, float* __restrict__ C, int Kdim, int ldC)
{
    extern __shared__ char smem[];
    uint32_t sb = smem_u32(smem);
    int tid = threadIdx.x;
    int w = tid >> 5, lane = tid & 31;
    int wm = w & 1, wn = w >> 1;            // warp tile 64x64: rows wm*64, cols wn*64
    int m0 = blockIdx.x * MBM2;             // M fast-varying for L2 reuse
    int n0 = blockIdx.y * MBN2;
    int nit = Kdim / MBK2;

    float acc[4][8][4];
#pragma unroll
    for (int a = 0; a < 4; a++)
#pragma unroll
        for (int b = 0; b < 8; b++)
#pragma unroll
            for (int c = 0; c < 4; c++) acc[a][b][c] = 0.f;

    auto load_stage = [&](int s, int k0) {
        uint32_t base = sb + s * STG2;
#pragma unroll
        for (int t = 0; t < 2; t++) {
            int idx = tid + t * 256;        // 0..511: 128 rows x 4 chunks
            int r = idx >> 2, c = idx & 3;
            uint32_t so = (uint32_t)(r * ROW2 + c * 16);
            size_t ga = (size_t)(m0 + r) * Kdim + k0 + c * 8;
            cp16(base + so, Ah + ga);
            cp16(base + ST_A + so, Al + ga);
        }
#pragma unroll
        for (int t = 0; t < 4; t++) {
            int idx = tid + t * 256;        // 0..1023: 256 rows x 4 chunks
            int r = idx >> 2, c = idx & 3;
            uint32_t so = (uint32_t)(r * ROW2 + c * 16);
            size_t gb = (size_t)(n0 + r) * Kdim + k0 + c * 8;
            cp16(base + 2 * ST_A + so, Bh + gb);
            cp16(base + 2 * ST_A + ST_B + so, Bl + gb);
        }
        CP_COMMIT();
    };

    load_stage(0, 0);
    if (nit > 1) load_stage(1, MBK2);

    int lr = lane & 15, lc = lane >> 4;
#pragma unroll 1
    for (int i = 0; i < nit; i++) {
        if (i + 2 < nit) { load_stage((i + 2) % NSTG, (i + 2) * MBK2); CP_WAIT(2); }
        else if (i + 1 < nit) CP_WAIT(1);
        else CP_WAIT(0);
        __syncthreads();

        uint32_t base = sb + (i % NSTG) * STG2;
#pragma unroll
        for (int kh = 0; kh < 2; kh++) {
            uint32_t colB = (uint32_t)((kh * 16 + lc * 8) * 2);
            uint32_t ra_h[4][4], ra_l[4][4], rb_h[4][4], rb_l[4][4];
#pragma unroll
            for (int mt = 0; mt < 4; mt++)
                ldmx4(ra_h[mt], base + (uint32_t)((wm * 64 + mt * 16 + lr) * ROW2) + colB);
#pragma unroll
            for (int np = 0; np < 4; np++)
                ldmx4(rb_h[np], base + 2 * ST_A +
                      (uint32_t)((wn * 64 + np * 16 + lr) * ROW2) + colB);
            // pass hh: 32 quads touched once each
#pragma unroll
            for (int mt = 0; mt < 4; mt++)
#pragma unroll
                for (int np = 0; np < 4; np++) {
                    mma16816(acc[mt][2 * np],     ra_h[mt], rb_h[np][0], rb_h[np][2]);
                    mma16816(acc[mt][2 * np + 1], ra_h[mt], rb_h[np][1], rb_h[np][3]);
                }
            // load A-lo, pass lh
#pragma unroll
            for (int mt = 0; mt < 4; mt++)
                ldmx4(ra_l[mt], base + ST_A +
                      (uint32_t)((wm * 64 + mt * 16 + lr) * ROW2) + colB);
#pragma unroll
            for (int mt = 0; mt < 4; mt++)
#pragma unroll
                for (int np = 0; np < 4; np++) {
                    mma16816(acc[mt][2 * np],     ra_l[mt], rb_h[np][0], rb_h[np][2]);
                    mma16816(acc[mt][2 * np + 1], ra_l[mt], rb_h[np][1], rb_h[np][3]);
                }
            // load B-lo, pass hl
#pragma unroll
            for (int np = 0; np < 4; np++)
                ldmx4(rb_l[np], base + 2 * ST_A + ST_B +
                      (uint32_t)((wn * 64 + np * 16 + lr) * ROW2) + colB);
#pragma unroll
            for (int mt = 0; mt < 4; mt++)
#pragma unroll
                for (int np = 0; np < 4; np++) {
                    mma16816(acc[mt][2 * np],     ra_h[mt], rb_l[np][0], rb_l[np][2]);
                    mma16816(acc[mt][2 * np + 1], ra_h[mt], rb_l[np][1], rb_l[np][3]);
                }
        }
        __syncthreads();
    }

    // epilogue: direct stores with bias (+ optional relu)
    int qr = lane >> 2, qc = lane & 3;
    float bv[8][2];
#pragma unroll
    for (int nt = 0; nt < 8; nt++) {
        int cidx = n0 + wn * 64 + nt * 8 + qc * 2;
        bv[nt][0] = __ldg(bias + cidx);
        bv[nt][1] = __ldg(bias + cidx + 1);
    }
#pragma unroll
    for (int mt = 0; mt < 4; mt++) {
        int r0 = m0 + wm * 64 + mt * 16 + qr;
#pragma unroll
        for (int nt = 0; nt < 8; nt++) {
            int cidx = n0 + wn * 64 + nt * 8 + qc * 2;
            float2 v0 = make_float2(acc[mt][nt][0] + bv[nt][0], acc[mt][nt][1] + bv[nt][1]);
            float2 v1 = make_float2(acc[mt][nt][2] + bv[nt][0], acc[mt][nt][3] + bv[nt][1]);
            if (RELU) {
                v0.x = fmaxf(v0.x, 0.f); v0.y = fmaxf(v0.y, 0.f);
                v1.x = fmaxf(v1.x, 0.f); v1.y = fmaxf(v1.y, 0.f);
            }
            *(float2*)(C + (size_t)r0 * ldC + cidx) = v0;
            *(float2*)(C + (size_t)(r0 + 8) * ldC + cidx) = v1;
        }
    }
}

// ---------------- block reduce ------------------------------------------------
__device__ __forceinline__ float blockReduce(float v, bool domax) {
    __shared__ float sh[8];
    int lane = threadIdx.x & 31;
    int wp = threadIdx.x >> 5;
#pragma unroll
    for (int o = 16; o; o >>= 1) {
        float t = __shfl_xor_sync(0xffffffffu, v, o);
        v = domax ? fmaxf(v, t) : (v + t);
    }
    if (lane == 0) sh[wp] = v;
    __syncthreads();
    float r = sh[lane & 7];
#pragma unroll
    for (int o = 4; o; o >>= 1) {
        float t = __shfl_xor_sync(0xffffffffu, r, o);
        r = domax ? fmaxf(r, t) : (r + t);
    }
    __syncthreads();
    return r;
}

// ------------- fused gate features + sigmoid + mix (in place on out) ----------
__global__ void k_gatemix(float* __restrict__ out,
                          const float* __restrict__ gw,
                          const float* __restrict__ gb)
{
    int row = blockIdx.x;
    float feats[6];
    const float* srcs[2];
    srcs[0] = out + (size_t)row * VV;
    srcs[1] = g_loc + (size_t)row * VV;
    for (int s = 0; s < 2; s++) {
        const float4* p = (const float4*)srcs[s];
        float mx = -INFINITY, sum = 0.f, sq = 0.f;
        for (int i = threadIdx.x; i < VV / 4; i += 256) {
            float4 v = p[i];
            mx = fmaxf(mx, fmaxf(fmaxf(v.x, v.y), fmaxf(v.z, v.w)));
            sum += (v.x + v.y) + (v.z + v.w);
            sq += v.x * v.x + v.y * v.y + v.z * v.z + v.w * v.w;
        }
        mx  = blockReduce(mx, true);
        sum = blockReduce(sum, false);
        sq  = blockReduce(sq, false);
        float se = 0.f, sl = 0.f;
        for (int i = threadIdx.x; i < VV / 4; i += 256) {
            float4 v = p[i];
            float e;
            e = __expf(v.x - mx); se += e; sl += e * v.x;
            e = __expf(v.y - mx); se += e; sl += e * v.y;
            e = __expf(v.z - mx); se += e; sl += e * v.z;
            e = __expf(v.w - mx); se += e; sl += e * v.w;
        }
        se = blockReduce(se, false);
        sl = blockReduce(sl, false);
        float lse = mx + logf(se);
        float ent = lse - sl / se;
        float mean = sum * (1.f / VV);
        float var = sq * (1.f / VV) - mean * mean;
        feats[s * 3 + 0] = ent;
        feats[s * 3 + 1] = mx;
        feats[s * 3 + 2] = var;
    }
    float z = __ldg(gb);
#pragma unroll
    for (int i = 0; i < 6; i++) z = fmaf(feats[i], __ldg(gw + i), z);
    float g = 1.f / (1.f + expf(-z));

    float4* po = (float4*)srcs[0];
    const float4* pc = (const float4*)srcs[1];
    for (int i = threadIdx.x; i < VV / 4; i += 256) {
        float4 a = po[i];
        float4 c = pc[i];
        float4 r;
        r.x = fmaf(g, a.x - c.x, c.x);
        r.y = fmaf(g, a.y - c.y, c.y);
        r.z = fmaf(g, a.z - c.z, c.z);
        r.w = fmaf(g, a.w - c.w, c.w);
        po[i] = r;
    }
}

// ---------------- launcher ----------------------------------------------------
extern "C" void kernel_launch(void* const* d_in, const int* in_sizes, int n_in,
                              void* d_out, int out_size)
{
    const int*   chars   = (const int*)  d_in[0];
    const float* emb     = (const float*)d_in[1];
    const float* in_proj = (const float*)d_in[2];
    const float* decays  = (const float*)d_in[3];
    const float* lin_W1  = (const float*)d_in[4];
    const float* lin_b1  = (const float*)d_in[5];
    const float* lin_W2  = (const float*)d_in[6];
    const float* lin_b2  = (const float*)d_in[7];
    const float* loc_W1  = (const float*)d_in[8];
    const float* loc_b1  = (const float*)d_in[9];
    const float* loc_W2  = (const float*)d_in[10];
    const float* loc_b2  = (const float*)d_in[11];
    const float* gate_W  = (const float*)d_in[12];
    const float* gate_b  = (const float*)d_in[13];
    float* out = (float*)d_out;

    float *px, *pdrive, *pz, *ph, *pstk, *ploc;
    __nv_bfloat16 *pah, *pal, *pzh, *pzl, *psh, *psl;
    __nv_bfloat16 *pwlh, *pwll, *pwch, *pwcl, *pw1lh, *pw1ll, *pw1ch, *pw1cl;
    cudaGetSymbolAddress((void**)&px,     g_x);
    cudaGetSymbolAddress((void**)&pdrive, g_drive);
    cudaGetSymbolAddress((void**)&pz,     g_z);
    cudaGetSymbolAddress((void**)&ph,     g_h);
    cudaGetSymbolAddress((void**)&pstk,   g_stacked);
    cudaGetSymbolAddress((void**)&ploc,   g_loc);
    cudaGetSymbolAddress((void**)&pah,    g_ah);
    cudaGetSymbolAddress((void**)&pal,    g_al);
    cudaGetSymbolAddress((void**)&pzh,    g_zh);
    cudaGetSymbolAddress((void**)&pzl,    g_zl);
    cudaGetSymbolAddress((void**)&psh,    g_sh);
    cudaGetSymbolAddress((void**)&psl,    g_sl);
    cudaGetSymbolAddress((void**)&pwlh,   g_wl_h);
    cudaGetSymbolAddress((void**)&pwll,   g_wl_l);
    cudaGetSymbolAddress((void**)&pwch,   g_wc_h);
    cudaGetSymbolAddress((void**)&pwcl,   g_wc_l);
    cudaGetSymbolAddress((void**)&pw1lh,  g_w1l_h);
    cudaGetSymbolAddress((void**)&pw1ll,  g_w1l_l);
    cudaGetSymbolAddress((void**)&pw1ch,  g_w1c_h);
    cudaGetSymbolAddress((void**)&pw1cl,  g_w1c_l);

    static bool attr_set = false;
    if (!attr_set) {
        cudaFuncSetAttribute(k_mma2<false>, cudaFuncAttributeMaxDynamicSharedMemorySize, MSMEM2);
        cudaFuncSetAttribute(k_mma2<true>,  cudaFuncAttributeMaxDynamicSharedMemorySize, MSMEM2);
        attr_set = true;
    }

    // weight transpose+split (front-loaded)
    k_wsplitT<<<dim3(VV / 32, HH / 32), dim3(32, 8)>>>(lin_W2, pwlh, pwll, HH, VV);
    k_wsplitT<<<dim3(VV / 32, HH / 32), dim3(32, 8)>>>(loc_W2, pwch, pwcl, HH, VV);
    k_wsplitT<<<dim3(HH / 32, ZK / 32), dim3(32, 8)>>>(lin_W1, pw1lh, pw1ll, ZK, HH);
    k_wsplitT<<<dim3(HH / 32, SK / 32), dim3(32, 8)>>>(loc_W1, pw1ch, pw1cl, SK, HH);

    // 1) embed (also fills z[:,256:512])
    k_embed<<<RR, 64>>>(chars, emb);

    // 2) drive = x @ in_proj (SIMT; small)
    k_gemm<<<dim3(MM / GBN, RR / GBM), 256>>>(px, in_proj, pdrive, MM, EE);

    // 3) decay scan -> z[:,0:256]
    k_scan<<<2, 256>>>(decays);

    // 4) windowed stack
    k_stack<<<dim3(RR, WW), 64>>>();

    // splits of activations
    k_asplit<<<RR * ZK / 4 / 256, 256>>>(pz, pzh, pzl, RR * ZK / 4);
    k_asplit<<<RR * SK / 4 / 256, 256>>>(pstk, psh, psl, RR * SK / 4);

    // 5) lin hidden = relu(z @ lin_W1 + b1) via mma
    k_mma2<true><<<dim3(RR / MBM2, HH / MBN2), 256, MSMEM2>>>(
        pzh, pzl, pw1lh, pw1ll, lin_b1, ph, ZK, HH);

    // 6) split lin hidden, lin logits -> d_out
    k_asplit<<<RR * HH / 4 / 256, 256>>>(ph, pah, pal, RR * HH / 4);
    k_mma2<false><<<dim3(RR / MBM2, VV / MBN2), 256, MSMEM2>>>(
        pah, pal, pwlh, pwll, lin_b2, out, HH, VV);

    // 7) loc hidden = relu(stacked @ loc_W1 + b1) via mma
    k_mma2<true><<<dim3(RR / MBM2, HH / MBN2), 256, MSMEM2>>>(
        psh, psl, pw1ch, pw1cl, loc_b1, ph, SK, HH);

    // 8) split loc hidden, loc logits -> g_loc
    k_asplit<<<RR * HH / 4 / 256, 256>>>(ph, pah, pal, RR * HH / 4);
    k_mma2<false><<<dim3(RR / MBM2, VV / MBN2), 256, MSMEM2>>>(
        pah, pal, pwch, pwcl, loc_b2, ploc, HH, VV);

    // 9) fused gate + mix (in place on d_out)
    k_gatemix<<<RR, 256>>>(out, gate_W, gate_b);
}

// round 7
// speedup vs baseline: 2.1566x; 1.1437x over previous
#include <cuda_runtime.h>
#include <cuda_bf16.h>
#include <math.h>
#include <stdint.h>

// Problem dims (fixed)
#define BB 2
#define TT 1024
#define RR 2048          // B*T rows
#define EE 256
#define MM 256
#define HH 1024
#define VV 32000
#define WW 8
#define ZK 512           // M+E
#define SK 2048          // W*E

// ================= PTX helpers (arch-agnostic only!) ==========================
__device__ __forceinline__ uint32_t smem_u32(const void* p) {
    uint32_t a;
    asm("{ .reg .u64 t; cvta.to.shared.u64 t, %1; cvt.u32.u64 %0, t; }" : "=r"(a) : "l"(p));
    return a;
}
__device__ __forceinline__ void cp16(uint32_t saddr, const void* g) {
    asm volatile("cp.async.cg.shared.global [%0], [%1], 16;\n" :: "r"(saddr), "l"(g));
}
#define CP_COMMIT() asm volatile("cp.async.commit_group;\n" ::: "memory")
#define CP_WAIT(n)  asm volatile("cp.async.wait_group %0;\n" :: "n"(n) : "memory")

__device__ __forceinline__ void ldmx4(uint32_t* r, uint32_t addr) {
    asm volatile("ldmatrix.sync.aligned.m8n8.x4.shared.b16 {%0,%1,%2,%3}, [%4];"
        : "=r"(r[0]), "=r"(r[1]), "=r"(r[2]), "=r"(r[3]) : "r"(addr));
}
__device__ __forceinline__ void mma16816(float* c, const uint32_t* a,
                                         uint32_t b0, uint32_t b1) {
    asm volatile("mma.sync.aligned.m16n8k16.row.col.f32.bf16.bf16.f32 "
        "{%0,%1,%2,%3}, {%4,%5,%6,%7}, {%8,%9}, {%0,%1,%2,%3};"
        : "+f"(c[0]), "+f"(c[1]), "+f"(c[2]), "+f"(c[3])
        : "r"(a[0]), "r"(a[1]), "r"(a[2]), "r"(a[3]), "r"(b0), "r"(b1));
}
__device__ __forceinline__ __nv_bfloat162 split_hi2(float x, float y, float& rx, float& ry) {
    __nv_bfloat16 hx = __float2bfloat16(x), hy = __float2bfloat16(y);
    rx = x - __bfloat162float(hx);
    ry = y - __bfloat162float(hy);
    return __nv_bfloat162(hx, hy);
}

// ---------------- scratch (device globals; no allocation allowed) -------------
__device__ float g_x[RR * EE];
__device__ float g_drive[RR * MM];
__device__ float g_loc[(size_t)RR * VV];
// bf16 split activation buffers
__device__ __nv_bfloat16 g_zh[RR * ZK];             // [states | x] hi
__device__ __nv_bfloat16 g_zl[RR * ZK];
__device__ __nv_bfloat16 g_sh[RR * SK];             // stacked hi
__device__ __nv_bfloat16 g_sl[RR * SK];
__device__ __nv_bfloat16 g_ah[RR * HH];             // lin hidden hi/lo
__device__ __nv_bfloat16 g_al[RR * HH];
__device__ __nv_bfloat16 g_bh[RR * HH];             // loc hidden hi/lo
__device__ __nv_bfloat16 g_bl[RR * HH];
// bf16 split transposed weights [N,K]
__device__ __nv_bfloat16 g_wl_h[(size_t)VV * HH];
__device__ __nv_bfloat16 g_wl_l[(size_t)VV * HH];
__device__ __nv_bfloat16 g_wc_h[(size_t)VV * HH];
__device__ __nv_bfloat16 g_wc_l[(size_t)VV * HH];
__device__ __nv_bfloat16 g_w1l_h[HH * ZK];
__device__ __nv_bfloat16 g_w1l_l[HH * ZK];
__device__ __nv_bfloat16 g_w1c_h[(size_t)HH * SK];
__device__ __nv_bfloat16 g_w1c_l[(size_t)HH * SK];

// -------- embed: x fp32 (for drive/stack) + z[:,256:512] split bf16 ----------
__global__ void k_embed(const int* __restrict__ chars, const float* __restrict__ emb) {
    int row = blockIdx.x;
    int c = chars[row];
    const float4* src = (const float4*)(emb + (size_t)c * EE);
    float4* dx = (float4*)(g_x + (size_t)row * EE);
    int i = threadIdx.x;            // 64 threads * float4
    float4 v = src[i];
    dx[i] = v;
    float lx, ly, lz, lw;
    __nv_bfloat162 h01 = split_hi2(v.x, v.y, lx, ly);
    __nv_bfloat162 h23 = split_hi2(v.z, v.w, lz, lw);
    size_t o = (size_t)row * ZK + MM + i * 4;
    ((__nv_bfloat162*)(g_zh + o))[0] = h01;
    ((__nv_bfloat162*)(g_zh + o))[1] = h23;
    ((__nv_bfloat162*)(g_zl + o))[0] = __nv_bfloat162(__float2bfloat16(lx), __float2bfloat16(ly));
    ((__nv_bfloat162*)(g_zl + o))[1] = __nv_bfloat162(__float2bfloat16(lz), __float2bfloat16(lw));
}

// -------- decay scan (fp32 state) -> z[:,0:256] split bf16 --------------------
__global__ void k_scan(const float* __restrict__ decays) {
    int idx = blockIdx.x * blockDim.x + threadIdx.x;
    if (idx >= BB * MM) return;
    int b = idx >> 8;
    int m = idx & 255;
    float d = decays[m];
    float s = 0.f;
    const float* dr = g_drive + (size_t)b * TT * MM + m;
    __nv_bfloat16* zh = g_zh + (size_t)b * TT * ZK + m;
    __nv_bfloat16* zl = g_zl + (size_t)b * TT * ZK + m;
    for (int t = 0; t < TT; t++) {
        s = fmaf(d, s, dr[(size_t)t * MM]);
        __nv_bfloat16 h = __float2bfloat16(s);
        zh[(size_t)t * ZK] = h;
        zl[(size_t)t * ZK] = __float2bfloat16(s - __bfloat162float(h));
    }
}

// -------- windowed stack -> split bf16 directly -------------------------------
__global__ void k_stack() {
    int row = blockIdx.x;
    int o = blockIdx.y;
    int t = row & (TT - 1);
    size_t dsto = (size_t)row * SK + o * EE + threadIdx.x * 4;
    __nv_bfloat162* dh = (__nv_bfloat162*)(g_sh + dsto);
    __nv_bfloat162* dl = (__nv_bfloat162*)(g_sl + dsto);
    if (t - o >= 0) {
        float4 v = ((const float4*)(g_x + (size_t)(row - o) * EE))[threadIdx.x];
        float lx, ly, lz, lw;
        dh[0] = split_hi2(v.x, v.y, lx, ly);
        dh[1] = split_hi2(v.z, v.w, lz, lw);
        dl[0] = __nv_bfloat162(__float2bfloat16(lx), __float2bfloat16(ly));
        dl[1] = __nv_bfloat162(__float2bfloat16(lz), __float2bfloat16(lw));
    } else {
        __nv_bfloat162 zz(__float2bfloat16(0.f), __float2bfloat16(0.f));
        dh[0] = zz; dh[1] = zz; dl[0] = zz; dl[1] = zz;
    }
}

// ---------------- SIMT fp32 GEMM (drive only) ---------------------------------
#define GBM 128
#define GBN 128
#define GBK 16
__global__ __launch_bounds__(256, 2) void k_gemm(
    const float* __restrict__ A, const float* __restrict__ B,
    float* __restrict__ C, int Ndim, int Kdim)
{
    __shared__ float As[GBK][GBM + 4];
    __shared__ float Bs[GBK][GBN + 4];
    int tid = threadIdx.x;
    int m0 = blockIdx.y * GBM;
    int n0 = blockIdx.x * GBN;
    int ty = tid >> 4, tx = tid & 15;
    float acc[8][8];
#pragma unroll
    for (int i = 0; i < 8; i++)
#pragma unroll
        for (int j = 0; j < 8; j++) acc[i][j] = 0.f;
    for (int k0 = 0; k0 < Kdim; k0 += GBK) {
#pragma unroll
        for (int r = 0; r < 2; r++) {
            int idx = tid + r * 256;
            int ar = idx >> 2, ac4 = idx & 3;
            float4 va = *(const float4*)(A + (size_t)(m0 + ar) * Kdim + k0 + ac4 * 4);
            As[ac4 * 4 + 0][ar] = va.x;
            As[ac4 * 4 + 1][ar] = va.y;
            As[ac4 * 4 + 2][ar] = va.z;
            As[ac4 * 4 + 3][ar] = va.w;
            int br = idx >> 5, bc4 = idx & 31;
            float4 vb = *(const float4*)(B + (size_t)(k0 + br) * Ndim + n0 + bc4 * 4);
            *(float4*)&Bs[br][bc4 * 4] = vb;
        }
        __syncthreads();
#pragma unroll
        for (int kk = 0; kk < GBK; kk++) {
            float a[8], b[8];
            *(float4*)&a[0] = *(const float4*)&As[kk][ty * 8];
            *(float4*)&a[4] = *(const float4*)&As[kk][ty * 8 + 4];
            *(float4*)&b[0] = *(const float4*)&Bs[kk][tx * 8];
            *(float4*)&b[4] = *(const float4*)&Bs[kk][tx * 8 + 4];
#pragma unroll
            for (int i = 0; i < 8; i++)
#pragma unroll
                for (int j = 0; j < 8; j++)
                    acc[i][j] = fmaf(a[i], b[j], acc[i][j]);
        }
        __syncthreads();
    }
#pragma unroll
    for (int i = 0; i < 8; i++) {
        int m = m0 + ty * 8 + i;
#pragma unroll
        for (int j = 0; j < 8; j += 4) {
            int n = n0 + tx * 8 + j;
            float4 v;
            v.x = acc[i][j + 0]; v.y = acc[i][j + 1];
            v.z = acc[i][j + 2]; v.w = acc[i][j + 3];
            *(float4*)(C + (size_t)m * Ndim + n) = v;
        }
    }
}

// ---------- transpose + split W[Krows, Ncols] -> Wt[N,K] hi/lo ----------------
__global__ void k_wsplitT(const float* __restrict__ Wsrc,
                          __nv_bfloat16* __restrict__ Th,
                          __nv_bfloat16* __restrict__ Tl,
                          int Krows, int Ncols) {
    __shared__ float tile[32][33];
    int n0 = blockIdx.x * 32;
    int k0 = blockIdx.y * 32;
    int tx = threadIdx.x, ty = threadIdx.y;   // 32 x 8
#pragma unroll
    for (int r = 0; r < 32; r += 8)
        tile[ty + r][tx] = Wsrc[(size_t)(k0 + ty + r) * Ncols + n0 + tx];
    __syncthreads();
#pragma unroll
    for (int r = 0; r < 32; r += 8) {
        float v = tile[tx][ty + r];
        __nv_bfloat16 h = __float2bfloat16(v);
        __nv_bfloat16 l = __float2bfloat16(v - __bfloat162float(h));
        size_t o = (size_t)(n0 + ty + r) * Krows + k0 + tx;
        Th[o] = h;
        Tl[o] = l;
    }
}

// ====== split-bf16 mma.sync GEMM, 2 CTAs/SM: tile 128x128, BK=32, 2 stages ====
#define MBM3 128
#define MBN3 128
#define MBK3 32
#define ROW3 80                          // padded row stride bytes (40 bf16)
#define TIL3 (128 * ROW3)                // 10240
#define STG3 (4 * TIL3)                  // Ah,Al,Bh,Bl = 40960
#define MSMEM3 (2 * STG3)                // 81920

template<bool RELU, bool SPLITOUT>
__global__ __launch_bounds__(256, 2) void k_mma3(
    const __nv_bfloat16* __restrict__ Ah, const __nv_bfloat16* __restrict__ Al,
    const __nv_bfloat16* __restrict__ Bh, const __nv_bfloat16* __restrict__ Bl,
    const float* __restrict__ bias, float* __restrict__ C,
    __nv_bfloat16* __restrict__ Oh, __nv_bfloat16* __restrict__ Ol,
    int Kdim, int ldC)
{
    extern __shared__ char smem[];
    uint32_t sb = smem_u32(smem);
    int tid = threadIdx.x;
    int w = tid >> 5, lane = tid & 31;
    int wm = w & 3, wn = w >> 2;            // warp tile 32x64
    int m0 = blockIdx.x * MBM3;             // M fast-varying for L2 reuse of B
    int n0 = blockIdx.y * MBN3;
    int nit = Kdim / MBK3;

    float acc[2][8][4];
#pragma unroll
    for (int a = 0; a < 2; a++)
#pragma unroll
        for (int b = 0; b < 8; b++)
#pragma unroll
            for (int c = 0; c < 4; c++) acc[a][b][c] = 0.f;

    auto load_stage = [&](int s, int k0) {
        uint32_t base = sb + s * STG3;
#pragma unroll
        for (int t = 0; t < 2; t++) {
            int idx = tid + t * 256;        // 0..511
            int r = idx >> 2, c = idx & 3;
            uint32_t so = (uint32_t)(r * ROW3 + c * 16);
            size_t ga = (size_t)(m0 + r) * Kdim + k0 + c * 8;
            cp16(base + so, Ah + ga);
            cp16(base + TIL3 + so, Al + ga);
            size_t gb = (size_t)(n0 + r) * Kdim + k0 + c * 8;
            cp16(base + 2 * TIL3 + so, Bh + gb);
            cp16(base + 3 * TIL3 + so, Bl + gb);
        }
        CP_COMMIT();
    };

    load_stage(0, 0);

    int lr = lane & 15, lc = lane >> 4;
#pragma unroll 1
    for (int i = 0; i < nit; i++) {
        int s = i & 1;
        if (i + 1 < nit) { load_stage(s ^ 1, (i + 1) * MBK3); CP_WAIT(1); }
        else CP_WAIT(0);
        __syncthreads();

        uint32_t base = sb + s * STG3;
#pragma unroll
        for (int kh = 0; kh < 2; kh++) {
            uint32_t colB = (uint32_t)((kh * 16 + lc * 8) * 2);
            uint32_t ra_h[2][4], ra_l[2][4], rb_h[4][4], rb_l[4][4];
#pragma unroll
            for (int mt = 0; mt < 2; mt++)
                ldmx4(ra_h[mt], base + (uint32_t)((wm * 32 + mt * 16 + lr) * ROW3) + colB);
#pragma unroll
            for (int np = 0; np < 4; np++)
                ldmx4(rb_h[np], base + 2 * TIL3 +
                      (uint32_t)((wn * 64 + np * 16 + lr) * ROW3) + colB);
            // pass hh
#pragma unroll
            for (int mt = 0; mt < 2; mt++)
#pragma unroll
                for (int np = 0; np < 4; np++) {
                    mma16816(acc[mt][2 * np],     ra_h[mt], rb_h[np][0], rb_h[np][2]);
                    mma16816(acc[mt][2 * np + 1], ra_h[mt], rb_h[np][1], rb_h[np][3]);
                }
            // pass lh
#pragma unroll
            for (int mt = 0; mt < 2; mt++)
                ldmx4(ra_l[mt], base + TIL3 +
                      (uint32_t)((wm * 32 + mt * 16 + lr) * ROW3) + colB);
#pragma unroll
            for (int mt = 0; mt < 2; mt++)
#pragma unroll
                for (int np = 0; np < 4; np++) {
                    mma16816(acc[mt][2 * np],     ra_l[mt], rb_h[np][0], rb_h[np][2]);
                    mma16816(acc[mt][2 * np + 1], ra_l[mt], rb_h[np][1], rb_h[np][3]);
                }
            // pass hl
#pragma unroll
            for (int np = 0; np < 4; np++)
                ldmx4(rb_l[np], base + 3 * TIL3 +
                      (uint32_t)((wn * 64 + np * 16 + lr) * ROW3) + colB);
#pragma unroll
            for (int mt = 0; mt < 2; mt++)
#pragma unroll
                for (int np = 0; np < 4; np++) {
                    mma16816(acc[mt][2 * np],     ra_h[mt], rb_l[np][0], rb_l[np][2]);
                    mma16816(acc[mt][2 * np + 1], ra_h[mt], rb_l[np][1], rb_l[np][3]);
                }
        }
        __syncthreads();
    }

    // epilogue
    int qr = lane >> 2, qc = lane & 3;
#pragma unroll
    for (int mt = 0; mt < 2; mt++) {
        int r0 = m0 + wm * 32 + mt * 16 + qr;
#pragma unroll
        for (int nt = 0; nt < 8; nt++) {
            int cidx = n0 + wn * 64 + nt * 8 + qc * 2;
            float b0 = __ldg(bias + cidx), b1 = __ldg(bias + cidx + 1);
            float v00 = acc[mt][nt][0] + b0, v01 = acc[mt][nt][1] + b1;
            float v10 = acc[mt][nt][2] + b0, v11 = acc[mt][nt][3] + b1;
            if (RELU) {
                v00 = fmaxf(v00, 0.f); v01 = fmaxf(v01, 0.f);
                v10 = fmaxf(v10, 0.f); v11 = fmaxf(v11, 0.f);
            }
            if (SPLITOUT) {
                float l0, l1;
                __nv_bfloat162 h = split_hi2(v00, v01, l0, l1);
                *(__nv_bfloat162*)(Oh + (size_t)r0 * ldC + cidx) = h;
                *(__nv_bfloat162*)(Ol + (size_t)r0 * ldC + cidx) =
                    __nv_bfloat162(__float2bfloat16(l0), __float2bfloat16(l1));
                h = split_hi2(v10, v11, l0, l1);
                *(__nv_bfloat162*)(Oh + (size_t)(r0 + 8) * ldC + cidx) = h;
                *(__nv_bfloat162*)(Ol + (size_t)(r0 + 8) * ldC + cidx) =
                    __nv_bfloat162(__float2bfloat16(l0), __float2bfloat16(l1));
            } else {
                *(float2*)(C + (size_t)r0 * ldC + cidx) = make_float2(v00, v01);
                *(float2*)(C + (size_t)(r0 + 8) * ldC + cidx) = make_float2(v10, v11);
            }
        }
    }
}

// ---------------- block reduce ------------------------------------------------
__device__ __forceinline__ float blockReduce(float v, bool domax) {
    __shared__ float sh[8];
    int lane = threadIdx.x & 31;
    int wp = threadIdx.x >> 5;
#pragma unroll
    for (int o = 16; o; o >>= 1) {
        float t = __shfl_xor_sync(0xffffffffu, v, o);
        v = domax ? fmaxf(v, t) : (v + t);
    }
    if (lane == 0) sh[wp] = v;
    __syncthreads();
    float r = sh[lane & 7];
#pragma unroll
    for (int o = 4; o; o >>= 1) {
        float t = __shfl_xor_sync(0xffffffffu, r, o);
        r = domax ? fmaxf(r, t) : (r + t);
    }
    __syncthreads();
    return r;
}

// ------------- fused gate features + sigmoid + mix (in place on out) ----------
__global__ void k_gatemix(float* __restrict__ out,
                          const float* __restrict__ gw,
                          const float* __restrict__ gb)
{
    int row = blockIdx.x;
    float feats[6];
    const float* srcs[2];
    srcs[0] = out + (size_t)row * VV;
    srcs[1] = g_loc + (size_t)row * VV;
    for (int s = 0; s < 2; s++) {
        const float4* p = (const float4*)srcs[s];
        float mx = -INFINITY, sum = 0.f, sq = 0.f;
        for (int i = threadIdx.x; i < VV / 4; i += 256) {
            float4 v = p[i];
            mx = fmaxf(mx, fmaxf(fmaxf(v.x, v.y), fmaxf(v.z, v.w)));
            sum += (v.x + v.y) + (v.z + v.w);
            sq += v.x * v.x + v.y * v.y + v.z * v.z + v.w * v.w;
        }
        mx  = blockReduce(mx, true);
        sum = blockReduce(sum, false);
        sq  = blockReduce(sq, false);
        float se = 0.f, sl = 0.f;
        for (int i = threadIdx.x; i < VV / 4; i += 256) {
            float4 v = p[i];
            float e;
            e = __expf(v.x - mx); se += e; sl += e * v.x;
            e = __expf(v.y - mx); se += e; sl += e * v.y;
            e = __expf(v.z - mx); se += e; sl += e * v.z;
            e = __expf(v.w - mx); se += e; sl += e * v.w;
        }
        se = blockReduce(se, false);
        sl = blockReduce(sl, false);
        float lse = mx + logf(se);
        float ent = lse - sl / se;
        float mean = sum * (1.f / VV);
        float var = sq * (1.f / VV) - mean * mean;
        feats[s * 3 + 0] = ent;
        feats[s * 3 + 1] = mx;
        feats[s * 3 + 2] = var;
    }
    float z = __ldg(gb);
#pragma unroll
    for (int i = 0; i < 6; i++) z = fmaf(feats[i], __ldg(gw + i), z);
    float g = 1.f / (1.f + expf(-z));

    float4* po = (float4*)srcs[0];
    const float4* pc = (const float4*)srcs[1];
    for (int i = threadIdx.x; i < VV / 4; i += 256) {
        float4 a = po[i];
        float4 c = pc[i];
        float4 r;
        r.x = fmaf(g, a.x - c.x, c.x);
        r.y = fmaf(g, a.y - c.y, c.y);
        r.z = fmaf(g, a.z - c.z, c.z);
        r.w = fmaf(g, a.w - c.w, c.w);
        po[i] = r;
    }
}

// ---------------- launcher ----------------------------------------------------
extern "C" void kernel_launch(void* const* d_in, const int* in_sizes, int n_in,
                              void* d_out, int out_size)
{
    const int*   chars   = (const int*)  d_in[0];
    const float* emb     = (const float*)d_in[1];
    const float* in_proj = (const float*)d_in[2];
    const float* decays  = (const float*)d_in[3];
    const float* lin_W1  = (const float*)d_in[4];
    const float* lin_b1  = (const float*)d_in[5];
    const float* lin_W2  = (const float*)d_in[6];
    const float* lin_b2  = (const float*)d_in[7];
    const float* loc_W1  = (const float*)d_in[8];
    const float* loc_b1  = (const float*)d_in[9];
    const float* loc_W2  = (const float*)d_in[10];
    const float* loc_b2  = (const float*)d_in[11];
    const float* gate_W  = (const float*)d_in[12];
    const float* gate_b  = (const float*)d_in[13];
    float* out = (float*)d_out;

    float *px, *pdrive, *ploc;
    __nv_bfloat16 *pzh, *pzl, *psh, *psl, *pah, *pal, *pbh, *pbl;
    __nv_bfloat16 *pwlh, *pwll, *pwch, *pwcl, *pw1lh, *pw1ll, *pw1ch, *pw1cl;
    cudaGetSymbolAddress((void**)&px,     g_x);
    cudaGetSymbolAddress((void**)&pdrive, g_drive);
    cudaGetSymbolAddress((void**)&ploc,   g_loc);
    cudaGetSymbolAddress((void**)&pzh,    g_zh);
    cudaGetSymbolAddress((void**)&pzl,    g_zl);
    cudaGetSymbolAddress((void**)&psh,    g_sh);
    cudaGetSymbolAddress((void**)&psl,    g_sl);
    cudaGetSymbolAddress((void**)&pah,    g_ah);
    cudaGetSymbolAddress((void**)&pal,    g_al);
    cudaGetSymbolAddress((void**)&pbh,    g_bh);
    cudaGetSymbolAddress((void**)&pbl,    g_bl);
    cudaGetSymbolAddress((void**)&pwlh,   g_wl_h);
    cudaGetSymbolAddress((void**)&pwll,   g_wl_l);
    cudaGetSymbolAddress((void**)&pwch,   g_wc_h);
    cudaGetSymbolAddress((void**)&pwcl,   g_wc_l);
    cudaGetSymbolAddress((void**)&pw1lh,  g_w1l_h);
    cudaGetSymbolAddress((void**)&pw1ll,  g_w1l_l);
    cudaGetSymbolAddress((void**)&pw1ch,  g_w1c_h);
    cudaGetSymbolAddress((void**)&pw1cl,  g_w1c_l);

    static bool attr_set = false;
    if (!attr_set) {
        cudaFuncSetAttribute(k_mma3<false, false>, cudaFuncAttributeMaxDynamicSharedMemorySize, MSMEM3);
        cudaFuncSetAttribute(k_mma3<true,  true>,  cudaFuncAttributeMaxDynamicSharedMemorySize, MSMEM3);
        attr_set = true;
    }

    // 1) loc_W1 transpose+split
    k_wsplitT<<<dim3(HH / 32, SK / 32), dim3(32, 8)>>>(loc_W1, pw1ch, pw1cl, SK, HH);
    // 2) embed (x fp32 + z[:,256:512] bf16 split)
    k_embed<<<RR, 64>>>(chars, emb);
    // 3) windowed stack -> bf16 split
    k_stack<<<dim3(RR, WW), 64>>>();
    // 4) loc hidden = relu(stacked @ loc_W1 + b1) -> g_bh/g_bl   [PROFILED SLOT]
    k_mma3<true, true><<<dim3(RR / MBM3, HH / MBN3), 256, MSMEM3>>>(
        psh, psl, pw1ch, pw1cl, loc_b1, nullptr, pbh, pbl, SK, HH);
    // 5) drive = x @ in_proj (SIMT fp32)
    k_gemm<<<dim3(MM / GBN, RR / GBM), 256>>>(px, in_proj, pdrive, MM, EE);
    // 6) decay scan -> z[:,0:256] bf16 split
    k_scan<<<2, 256>>>(decays);
    // 7) lin_W1 transpose+split
    k_wsplitT<<<dim3(HH / 32, ZK / 32), dim3(32, 8)>>>(lin_W1, pw1lh, pw1ll, ZK, HH);
    // 8) lin hidden = relu(z @ lin_W1 + b1) -> g_ah/g_al
    k_mma3<true, true><<<dim3(RR / MBM3, HH / MBN3), 256, MSMEM3>>>(
        pzh, pzl, pw1lh, pw1ll, lin_b1, nullptr, pah, pal, ZK, HH);
    // 9) lin_W2 transpose+split
    k_wsplitT<<<dim3(VV / 32, HH / 32), dim3(32, 8)>>>(lin_W2, pwlh, pwll, HH, VV);
    // 10) lin logits -> d_out
    k_mma3<false, false><<<dim3(RR / MBM3, VV / MBN3), 256, MSMEM3>>>(
        pah, pal, pwlh, pwll, lin_b2, out, nullptr, nullptr, HH, VV);
    // 11) loc_W2 transpose+split
    k_wsplitT<<<dim3(VV / 32, HH / 32), dim3(32, 8)>>>(loc_W2, pwch, pwcl, HH, VV);
    // 12) loc logits -> g_loc
    k_mma3<false, false><<<dim3(RR / MBM3, VV / MBN3), 256, MSMEM3>>>(
        pbh, pbl, pwch, pwcl, loc_b2, ploc, nullptr, nullptr, HH, VV);
    // 13) fused gate + mix (in place on d_out)
    k_gatemix<<<RR, 256>>>(out, gate_W, gate_b);
}

// round 8
// speedup vs baseline: 3.7993x; 1.7617x over previous
#include <cuda_runtime.h>
#include <cuda_bf16.h>
#include <cuda_fp16.h>
#include <math.h>
#include <stdint.h>

// Problem dims (fixed)
#define BB 2
#define TT 1024
#define RR 2048          // B*T rows
#define EE 256
#define MM 256
#define HH 1024
#define VV 32000
#define WW 8
#define ZK 512           // M+E
#define SK 2048          // W*E

// ================= PTX helpers (arch-agnostic only!) ==========================
__device__ __forceinline__ uint32_t smem_u32(const void* p) {
    uint32_t a;
    asm("{ .reg .u64 t; cvta.to.shared.u64 t, %1; cvt.u32.u64 %0, t; }" : "=r"(a) : "l"(p));
    return a;
}
__device__ __forceinline__ void cp16(uint32_t saddr, const void* g) {
    asm volatile("cp.async.cg.shared.global [%0], [%1], 16;\n" :: "r"(saddr), "l"(g));
}
#define CP_COMMIT() asm volatile("cp.async.commit_group;\n" ::: "memory")
#define CP_WAIT(n)  asm volatile("cp.async.wait_group %0;\n" :: "n"(n) : "memory")

__device__ __forceinline__ void ldmx4(uint32_t* r, uint32_t addr) {
    asm volatile("ldmatrix.sync.aligned.m8n8.x4.shared.b16 {%0,%1,%2,%3}, [%4];"
        : "=r"(r[0]), "=r"(r[1]), "=r"(r[2]), "=r"(r[3]) : "r"(addr));
}
__device__ __forceinline__ void mma_bf16(float* c, const uint32_t* a,
                                         uint32_t b0, uint32_t b1) {
    asm volatile("mma.sync.aligned.m16n8k16.row.col.f32.bf16.bf16.f32 "
        "{%0,%1,%2,%3}, {%4,%5,%6,%7}, {%8,%9}, {%0,%1,%2,%3};"
        : "+f"(c[0]), "+f"(c[1]), "+f"(c[2]), "+f"(c[3])
        : "r"(a[0]), "r"(a[1]), "r"(a[2]), "r"(a[3]), "r"(b0), "r"(b1));
}
__device__ __forceinline__ void mma_f16(float* c, const uint32_t* a,
                                        uint32_t b0, uint32_t b1) {
    asm volatile("mma.sync.aligned.m16n8k16.row.col.f32.f16.f16.f32 "
        "{%0,%1,%2,%3}, {%4,%5,%6,%7}, {%8,%9}, {%0,%1,%2,%3};"
        : "+f"(c[0]), "+f"(c[1]), "+f"(c[2]), "+f"(c[3])
        : "r"(a[0]), "r"(a[1]), "r"(a[2]), "r"(a[3]), "r"(b0), "r"(b1));
}
__device__ __forceinline__ __nv_bfloat162 split_hi2(float x, float y, float& rx, float& ry) {
    __nv_bfloat16 hx = __float2bfloat16(x), hy = __float2bfloat16(y);
    rx = x - __bfloat162float(hx);
    ry = y - __bfloat162float(hy);
    return __nv_bfloat162(hx, hy);
}

// ---------------- scratch (device globals; no allocation allowed) -------------
__device__ float g_x[RR * EE];
__device__ float g_drive[RR * MM];
__device__ float g_loc[(size_t)RR * VV];
// bf16 split activations (hidden-layer inputs)
__device__ __nv_bfloat16 g_zh[RR * ZK];
__device__ __nv_bfloat16 g_zl[RR * ZK];
__device__ __nv_bfloat16 g_sh[RR * SK];
__device__ __nv_bfloat16 g_sl[RR * SK];
// fp16 hidden outputs + fp16 transposed W2
__device__ __half g_ha16[RR * HH];                  // lin hidden
__device__ __half g_hb16[RR * HH];                  // loc hidden
__device__ __half g_w16l[(size_t)VV * HH];          // lin_W2^T fp16 [N,K]
__device__ __half g_w16c[(size_t)VV * HH];          // loc_W2^T fp16
// bf16 split transposed W1
__device__ __nv_bfloat16 g_w1l_h[HH * ZK];
__device__ __nv_bfloat16 g_w1l_l[HH * ZK];
__device__ __nv_bfloat16 g_w1c_h[(size_t)HH * SK];
__device__ __nv_bfloat16 g_w1c_l[(size_t)HH * SK];

// -------- embed: x fp32 + z[:,256:512] split bf16 ----------------------------
__global__ void k_embed(const int* __restrict__ chars, const float* __restrict__ emb) {
    int row = blockIdx.x;
    int c = chars[row];
    const float4* src = (const float4*)(emb + (size_t)c * EE);
    float4* dx = (float4*)(g_x + (size_t)row * EE);
    int i = threadIdx.x;
    float4 v = src[i];
    dx[i] = v;
    float lx, ly, lz, lw;
    __nv_bfloat162 h01 = split_hi2(v.x, v.y, lx, ly);
    __nv_bfloat162 h23 = split_hi2(v.z, v.w, lz, lw);
    size_t o = (size_t)row * ZK + MM + i * 4;
    ((__nv_bfloat162*)(g_zh + o))[0] = h01;
    ((__nv_bfloat162*)(g_zh + o))[1] = h23;
    ((__nv_bfloat162*)(g_zl + o))[0] = __nv_bfloat162(__float2bfloat16(lx), __float2bfloat16(ly));
    ((__nv_bfloat162*)(g_zl + o))[1] = __nv_bfloat162(__float2bfloat16(lz), __float2bfloat16(lw));
}

// -------- decay scan -> z[:,0:256] split bf16 ---------------------------------
__global__ void k_scan(const float* __restrict__ decays) {
    int idx = blockIdx.x * blockDim.x + threadIdx.x;
    if (idx >= BB * MM) return;
    int b = idx >> 8;
    int m = idx & 255;
    float d = decays[m];
    float s = 0.f;
    const float* dr = g_drive + (size_t)b * TT * MM + m;
    __nv_bfloat16* zh = g_zh + (size_t)b * TT * ZK + m;
    __nv_bfloat16* zl = g_zl + (size_t)b * TT * ZK + m;
    for (int t = 0; t < TT; t++) {
        s = fmaf(d, s, dr[(size_t)t * MM]);
        __nv_bfloat16 h = __float2bfloat16(s);
        zh[(size_t)t * ZK] = h;
        zl[(size_t)t * ZK] = __float2bfloat16(s - __bfloat162float(h));
    }
}

// -------- windowed stack -> split bf16 ----------------------------------------
__global__ void k_stack() {
    int row = blockIdx.x;
    int o = blockIdx.y;
    int t = row & (TT - 1);
    size_t dsto = (size_t)row * SK + o * EE + threadIdx.x * 4;
    __nv_bfloat162* dh = (__nv_bfloat162*)(g_sh + dsto);
    __nv_bfloat162* dl = (__nv_bfloat162*)(g_sl + dsto);
    if (t - o >= 0) {
        float4 v = ((const float4*)(g_x + (size_t)(row - o) * EE))[threadIdx.x];
        float lx, ly, lz, lw;
        dh[0] = split_hi2(v.x, v.y, lx, ly);
        dh[1] = split_hi2(v.z, v.w, lz, lw);
        dl[0] = __nv_bfloat162(__float2bfloat16(lx), __float2bfloat16(ly));
        dl[1] = __nv_bfloat162(__float2bfloat16(lz), __float2bfloat16(lw));
    } else {
        __nv_bfloat162 zz(__float2bfloat16(0.f), __float2bfloat16(0.f));
        dh[0] = zz; dh[1] = zz; dl[0] = zz; dl[1] = zz;
    }
}

// ---------------- SIMT fp32 GEMM (drive only) ---------------------------------
#define GBM 128
#define GBN 128
#define GBK 16
__global__ __launch_bounds__(256, 2) void k_gemm(
    const float* __restrict__ A, const float* __restrict__ B,
    float* __restrict__ C, int Ndim, int Kdim)
{
    __shared__ float As[GBK][GBM + 4];
    __shared__ float Bs[GBK][GBN + 4];
    int tid = threadIdx.x;
    int m0 = blockIdx.y * GBM;
    int n0 = blockIdx.x * GBN;
    int ty = tid >> 4, tx = tid & 15;
    float acc[8][8];
#pragma unroll
    for (int i = 0; i < 8; i++)
#pragma unroll
        for (int j = 0; j < 8; j++) acc[i][j] = 0.f;
    for (int k0 = 0; k0 < Kdim; k0 += GBK) {
#pragma unroll
        for (int r = 0; r < 2; r++) {
            int idx = tid + r * 256;
            int ar = idx >> 2, ac4 = idx & 3;
            float4 va = *(const float4*)(A + (size_t)(m0 + ar) * Kdim + k0 + ac4 * 4);
            As[ac4 * 4 + 0][ar] = va.x;
            As[ac4 * 4 + 1][ar] = va.y;
            As[ac4 * 4 + 2][ar] = va.z;
            As[ac4 * 4 + 3][ar] = va.w;
            int br = idx >> 5, bc4 = idx & 31;
            float4 vb = *(const float4*)(B + (size_t)(k0 + br) * Ndim + n0 + bc4 * 4);
            *(float4*)&Bs[br][bc4 * 4] = vb;
        }
        __syncthreads();
#pragma unroll
        for (int kk = 0; kk < GBK; kk++) {
            float a[8], b[8];
            *(float4*)&a[0] = *(const float4*)&As[kk][ty * 8];
            *(float4*)&a[4] = *(const float4*)&As[kk][ty * 8 + 4];
            *(float4*)&b[0] = *(const float4*)&Bs[kk][tx * 8];
            *(float4*)&b[4] = *(const float4*)&Bs[kk][tx * 8 + 4];
#pragma unroll
            for (int i = 0; i < 8; i++)
#pragma unroll
                for (int j = 0; j < 8; j++)
                    acc[i][j] = fmaf(a[i], b[j], acc[i][j]);
        }
        __syncthreads();
    }
#pragma unroll
    for (int i = 0; i < 8; i++) {
        int m = m0 + ty * 8 + i;
#pragma unroll
        for (int j = 0; j < 8; j += 4) {
            int n = n0 + tx * 8 + j;
            float4 v;
            v.x = acc[i][j + 0]; v.y = acc[i][j + 1];
            v.z = acc[i][j + 2]; v.w = acc[i][j + 3];
            *(float4*)(C + (size_t)m * Ndim + n) = v;
        }
    }
}

// ---------- transpose + split W[Krows,Ncols] -> Wt[N,K] bf16 hi/lo ------------
__global__ void k_wsplitT(const float* __restrict__ Wsrc,
                          __nv_bfloat16* __restrict__ Th,
                          __nv_bfloat16* __restrict__ Tl,
                          int Krows, int Ncols) {
    __shared__ float tile[32][33];
    int n0 = blockIdx.x * 32;
    int k0 = blockIdx.y * 32;
    int tx = threadIdx.x, ty = threadIdx.y;
#pragma unroll
    for (int r = 0; r < 32; r += 8)
        tile[ty + r][tx] = Wsrc[(size_t)(k0 + ty + r) * Ncols + n0 + tx];
    __syncthreads();
#pragma unroll
    for (int r = 0; r < 32; r += 8) {
        float v = tile[tx][ty + r];
        __nv_bfloat16 h = __float2bfloat16(v);
        __nv_bfloat16 l = __float2bfloat16(v - __bfloat162float(h));
        size_t o = (size_t)(n0 + ty + r) * Krows + k0 + tx;
        Th[o] = h;
        Tl[o] = l;
    }
}

// ---------- transpose + convert W[Krows,Ncols] -> Wt[N,K] fp16 ----------------
__global__ void k_wconvT(const float* __restrict__ Wsrc,
                         __half* __restrict__ T, int Krows, int Ncols) {
    __shared__ float tile[32][33];
    int n0 = blockIdx.x * 32;
    int k0 = blockIdx.y * 32;
    int tx = threadIdx.x, ty = threadIdx.y;
#pragma unroll
    for (int r = 0; r < 32; r += 8)
        tile[ty + r][tx] = Wsrc[(size_t)(k0 + ty + r) * Ncols + n0 + tx];
    __syncthreads();
#pragma unroll
    for (int r = 0; r < 32; r += 8)
        T[(size_t)(n0 + ty + r) * Krows + k0 + tx] = __float2half_rn(tile[tx][ty + r]);
}

// ===== bf16 3-product hidden GEMM -> fp16 out; CTA tile CTAMx128, BK=32 =======
#define ROWP 80                          // padded row stride bytes (40 b16)
#define TILB (128 * ROWP)                // B tile (hi or lo) 10240 B

template<int CTAM, bool RELU>
__global__ __launch_bounds__(256, 2) void k_mma3(
    const __nv_bfloat16* __restrict__ Ah, const __nv_bfloat16* __restrict__ Al,
    const __nv_bfloat16* __restrict__ Bh, const __nv_bfloat16* __restrict__ Bl,
    const float* __restrict__ bias, __half* __restrict__ O,
    int Kdim, int ldO)
{
    constexpr int MROWS = CTAM / 32;     // warp M-positions
    constexpr int NP = MROWS;            // 16-col subtiles per warp
    constexpr int TILA = CTAM * ROWP;
    constexpr int STG = 2 * TILA + 2 * TILB;

    extern __shared__ char smem[];
    uint32_t sb = smem_u32(smem);
    int tid = threadIdx.x;
    int w = tid >> 5, lane = tid & 31;
    int wm = w % MROWS, wn = w / MROWS;
    int m0 = blockIdx.x * CTAM;
    int n0 = blockIdx.y * 128;
    int nit = Kdim / 32;

    float acc[2][2 * NP][4];
#pragma unroll
    for (int a = 0; a < 2; a++)
#pragma unroll
        for (int b = 0; b < 2 * NP; b++)
#pragma unroll
            for (int c = 0; c < 4; c++) acc[a][b][c] = 0.f;

    auto load_stage = [&](int s, int k0) {
        uint32_t base = sb + s * STG;
#pragma unroll
        for (int t = 0; t < CTAM / 64; t++) {
            int idx = tid + t * 256;
            int r = idx >> 2, c = idx & 3;
            uint32_t so = (uint32_t)(r * ROWP + c * 16);
            size_t ga = (size_t)(m0 + r) * Kdim + k0 + c * 8;
            cp16(base + so, Ah + ga);
            cp16(base + TILA + so, Al + ga);
        }
#pragma unroll
        for (int t = 0; t < 2; t++) {
            int idx = tid + t * 256;
            int r = idx >> 2, c = idx & 3;
            uint32_t so = (uint32_t)(r * ROWP + c * 16);
            size_t gb = (size_t)(n0 + r) * Kdim + k0 + c * 8;
            cp16(base + 2 * TILA + so, Bh + gb);
            cp16(base + 2 * TILA + TILB + so, Bl + gb);
        }
        CP_COMMIT();
    };

    load_stage(0, 0);

    int lr = lane & 15, lc = lane >> 4;
#pragma unroll 1
    for (int i = 0; i < nit; i++) {
        int s = i & 1;
        CP_WAIT(0);
        __syncthreads();
        if (i + 1 < nit) load_stage(s ^ 1, (i + 1) * 32);

        uint32_t base = sb + s * STG;
#pragma unroll
        for (int kh = 0; kh < 2; kh++) {
            uint32_t colB = (uint32_t)((kh * 16 + lc * 8) * 2);
            uint32_t ra_h[2][4], ra_l[2][4], rb_h[NP][4], rb_l[NP][4];
#pragma unroll
            for (int mt = 0; mt < 2; mt++)
                ldmx4(ra_h[mt], base + (uint32_t)((wm * 32 + mt * 16 + lr) * ROWP) + colB);
#pragma unroll
            for (int np = 0; np < NP; np++)
                ldmx4(rb_h[np], base + 2 * TILA +
                      (uint32_t)((wn * NP * 16 + np * 16 + lr) * ROWP) + colB);
#pragma unroll
            for (int mt = 0; mt < 2; mt++)
#pragma unroll
                for (int np = 0; np < NP; np++) {
                    mma_bf16(acc[mt][2 * np],     ra_h[mt], rb_h[np][0], rb_h[np][2]);
                    mma_bf16(acc[mt][2 * np + 1], ra_h[mt], rb_h[np][1], rb_h[np][3]);
                }
#pragma unroll
            for (int mt = 0; mt < 2; mt++)
                ldmx4(ra_l[mt], base + TILA +
                      (uint32_t)((wm * 32 + mt * 16 + lr) * ROWP) + colB);
#pragma unroll
            for (int mt = 0; mt < 2; mt++)
#pragma unroll
                for (int np = 0; np < NP; np++) {
                    mma_bf16(acc[mt][2 * np],     ra_l[mt], rb_h[np][0], rb_h[np][2]);
                    mma_bf16(acc[mt][2 * np + 1], ra_l[mt], rb_h[np][1], rb_h[np][3]);
                }
#pragma unroll
            for (int np = 0; np < NP; np++)
                ldmx4(rb_l[np], base + 2 * TILA + TILB +
                      (uint32_t)((wn * NP * 16 + np * 16 + lr) * ROWP) + colB);
#pragma unroll
            for (int mt = 0; mt < 2; mt++)
#pragma unroll
                for (int np = 0; np < NP; np++) {
                    mma_bf16(acc[mt][2 * np],     ra_h[mt], rb_l[np][0], rb_l[np][2]);
                    mma_bf16(acc[mt][2 * np + 1], ra_h[mt], rb_l[np][1], rb_l[np][3]);
                }
        }
        __syncthreads();
    }

    int qr = lane >> 2, qc = lane & 3;
#pragma unroll
    for (int mt = 0; mt < 2; mt++) {
        int r0 = m0 + wm * 32 + mt * 16 + qr;
#pragma unroll
        for (int nt = 0; nt < 2 * NP; nt++) {
            int cidx = n0 + wn * NP * 16 + nt * 8 + qc * 2;
            float b0 = __ldg(bias + cidx), b1 = __ldg(bias + cidx + 1);
            float v00 = acc[mt][nt][0] + b0, v01 = acc[mt][nt][1] + b1;
            float v10 = acc[mt][nt][2] + b0, v11 = acc[mt][nt][3] + b1;
            if (RELU) {
                v00 = fmaxf(v00, 0.f); v01 = fmaxf(v01, 0.f);
                v10 = fmaxf(v10, 0.f); v11 = fmaxf(v11, 0.f);
            }
            *(__half2*)(O + (size_t)r0 * ldO + cidx) = __floats2half2_rn(v00, v01);
            *(__half2*)(O + (size_t)(r0 + 8) * ldO + cidx) = __floats2half2_rn(v10, v11);
        }
    }
}

// ===== fp16 single-product logit GEMM: 128x128, BK=32, 4-stage ================
#define FTILA (128 * ROWP)               // 10240
#define FSTG (2 * FTILA)                 // Ah + Bh = 20480
#define FSMEM (4 * FSTG)                 // 81920

__global__ __launch_bounds__(256, 2) void k_mmaf16(
    const __half* __restrict__ A, const __half* __restrict__ B,
    const float* __restrict__ bias, float* __restrict__ C, int Kdim, int ldC)
{
    extern __shared__ char smem[];
    uint32_t sb = smem_u32(smem);
    int tid = threadIdx.x;
    int w = tid >> 5, lane = tid & 31;
    int wm = w & 3, wn = w >> 2;            // warp tile 32x64
    int m0 = blockIdx.x * 128;
    int n0 = blockIdx.y * 128;
    int nit = Kdim / 32;

    float acc[2][8][4];
#pragma unroll
    for (int a = 0; a < 2; a++)
#pragma unroll
        for (int b = 0; b < 8; b++)
#pragma unroll
            for (int c = 0; c < 4; c++) acc[a][b][c] = 0.f;

    auto load_stage = [&](int s, int k0) {
        uint32_t base = sb + s * FSTG;
#pragma unroll
        for (int t = 0; t < 2; t++) {
            int idx = tid + t * 256;
            int r = idx >> 2, c = idx & 3;
            uint32_t so = (uint32_t)(r * ROWP + c * 16);
            cp16(base + so, A + (size_t)(m0 + r) * Kdim + k0 + c * 8);
            cp16(base + FTILA + so, B + (size_t)(n0 + r) * Kdim + k0 + c * 8);
        }
        CP_COMMIT();
    };

    load_stage(0, 0);
    if (nit > 1) load_stage(1, 32);
    if (nit > 2) load_stage(2, 64);

    int lr = lane & 15, lc = lane >> 4;
#pragma unroll 1
    for (int i = 0; i < nit; i++) {
        int s = i & 3;
        CP_WAIT(2);
        __syncthreads();
        if (i + 3 < nit) load_stage((i + 3) & 3, (i + 3) * 32);

        uint32_t base = sb + s * FSTG;
#pragma unroll
        for (int kh = 0; kh < 2; kh++) {
            uint32_t colB = (uint32_t)((kh * 16 + lc * 8) * 2);
            uint32_t ra[2][4], rb[4][4];
#pragma unroll
            for (int mt = 0; mt < 2; mt++)
                ldmx4(ra[mt], base + (uint32_t)((wm * 32 + mt * 16 + lr) * ROWP) + colB);
#pragma unroll
            for (int np = 0; np < 4; np++)
                ldmx4(rb[np], base + FTILA +
                      (uint32_t)((wn * 64 + np * 16 + lr) * ROWP) + colB);
#pragma unroll
            for (int mt = 0; mt < 2; mt++)
#pragma unroll
                for (int np = 0; np < 4; np++) {
                    mma_f16(acc[mt][2 * np],     ra[mt], rb[np][0], rb[np][2]);
                    mma_f16(acc[mt][2 * np + 1], ra[mt], rb[np][1], rb[np][3]);
                }
        }
        __syncthreads();
    }

    int qr = lane >> 2, qc = lane & 3;
#pragma unroll
    for (int mt = 0; mt < 2; mt++) {
        int r0 = m0 + wm * 32 + mt * 16 + qr;
#pragma unroll
        for (int nt = 0; nt < 8; nt++) {
            int cidx = n0 + wn * 64 + nt * 8 + qc * 2;
            float b0 = __ldg(bias + cidx), b1 = __ldg(bias + cidx + 1);
            *(float2*)(C + (size_t)r0 * ldC + cidx) =
                make_float2(acc[mt][nt][0] + b0, acc[mt][nt][1] + b1);
            *(float2*)(C + (size_t)(r0 + 8) * ldC + cidx) =
                make_float2(acc[mt][nt][2] + b0, acc[mt][nt][3] + b1);
        }
    }
}

// ---------------- block reduce ------------------------------------------------
__device__ __forceinline__ float blockReduce(float v, bool domax) {
    __shared__ float sh[8];
    int lane = threadIdx.x & 31;
    int wp = threadIdx.x >> 5;
#pragma unroll
    for (int o = 16; o; o >>= 1) {
        float t = __shfl_xor_sync(0xffffffffu, v, o);
        v = domax ? fmaxf(v, t) : (v + t);
    }
    if (lane == 0) sh[wp] = v;
    __syncthreads();
    float r = sh[lane & 7];
#pragma unroll
    for (int o = 4; o; o >>= 1) {
        float t = __shfl_xor_sync(0xffffffffu, r, o);
        r = domax ? fmaxf(r, t) : (r + t);
    }
    __syncthreads();
    return r;
}

// ------------- fused gate features + sigmoid + mix ----------------------------
__global__ void k_gatemix(float* __restrict__ out,
                          const float* __restrict__ gw,
                          const float* __restrict__ gb)
{
    int row = blockIdx.x;
    float feats[6];
    const float* srcs[2];
    srcs[0] = out + (size_t)row * VV;
    srcs[1] = g_loc + (size_t)row * VV;
    for (int s = 0; s < 2; s++) {
        const float4* p = (const float4*)srcs[s];
        float mx = -INFINITY, sum = 0.f, sq = 0.f;
        for (int i = threadIdx.x; i < VV / 4; i += 256) {
            float4 v = p[i];
            mx = fmaxf(mx, fmaxf(fmaxf(v.x, v.y), fmaxf(v.z, v.w)));
            sum += (v.x + v.y) + (v.z + v.w);
            sq += v.x * v.x + v.y * v.y + v.z * v.z + v.w * v.w;
        }
        mx  = blockReduce(mx, true);
        sum = blockReduce(sum, false);
        sq  = blockReduce(sq, false);
        float se = 0.f, sl = 0.f;
        for (int i = threadIdx.x; i < VV / 4; i += 256) {
            float4 v = p[i];
            float e;
            e = __expf(v.x - mx); se += e; sl += e * v.x;
            e = __expf(v.y - mx); se += e; sl += e * v.y;
            e = __expf(v.z - mx); se += e; sl += e * v.z;
            e = __expf(v.w - mx); se += e; sl += e * v.w;
        }
        se = blockReduce(se, false);
        sl = blockReduce(sl, false);
        float lse = mx + logf(se);
        float ent = lse - sl / se;
        float mean = sum * (1.f / VV);
        float var = sq * (1.f / VV) - mean * mean;
        feats[s * 3 + 0] = ent;
        feats[s * 3 + 1] = mx;
        feats[s * 3 + 2] = var;
    }
    float z = __ldg(gb);
#pragma unroll
    for (int i = 0; i < 6; i++) z = fmaf(feats[i], __ldg(gw + i), z);
    float g = 1.f / (1.f + expf(-z));

    float4* po = (float4*)srcs[0];
    const float4* pc = (const float4*)srcs[1];
    for (int i = threadIdx.x; i < VV / 4; i += 256) {
        float4 a = po[i];
        float4 c = pc[i];
        float4 r;
        r.x = fmaf(g, a.x - c.x, c.x);
        r.y = fmaf(g, a.y - c.y, c.y);
        r.z = fmaf(g, a.z - c.z, c.z);
        r.w = fmaf(g, a.w - c.w, c.w);
        po[i] = r;
    }
}

// ---------------- launcher ----------------------------------------------------
extern "C" void kernel_launch(void* const* d_in, const int* in_sizes, int n_in,
                              void* d_out, int out_size)
{
    const int*   chars   = (const int*)  d_in[0];
    const float* emb     = (const float*)d_in[1];
    const float* in_proj = (const float*)d_in[2];
    const float* decays  = (const float*)d_in[3];
    const float* lin_W1  = (const float*)d_in[4];
    const float* lin_b1  = (const float*)d_in[5];
    const float* lin_W2  = (const float*)d_in[6];
    const float* lin_b2  = (const float*)d_in[7];
    const float* loc_W1  = (const float*)d_in[8];
    const float* loc_b1  = (const float*)d_in[9];
    const float* loc_W2  = (const float*)d_in[10];
    const float* loc_b2  = (const float*)d_in[11];
    const float* gate_W  = (const float*)d_in[12];
    const float* gate_b  = (const float*)d_in[13];
    float* out = (float*)d_out;

    float *px, *pdrive, *ploc;
    __nv_bfloat16 *pzh, *pzl, *psh, *psl;
    __nv_bfloat16 *pw1lh, *pw1ll, *pw1ch, *pw1cl;
    __half *pha, *phb, *pwl, *pwc;
    cudaGetSymbolAddress((void**)&px,     g_x);
    cudaGetSymbolAddress((void**)&pdrive, g_drive);
    cudaGetSymbolAddress((void**)&ploc,   g_loc);
    cudaGetSymbolAddress((void**)&pzh,    g_zh);
    cudaGetSymbolAddress((void**)&pzl,    g_zl);
    cudaGetSymbolAddress((void**)&psh,    g_sh);
    cudaGetSymbolAddress((void**)&psl,    g_sl);
    cudaGetSymbolAddress((void**)&pha,    g_ha16);
    cudaGetSymbolAddress((void**)&phb,    g_hb16);
    cudaGetSymbolAddress((void**)&pwl,    g_w16l);
    cudaGetSymbolAddress((void**)&pwc,    g_w16c);
    cudaGetSymbolAddress((void**)&pw1lh,  g_w1l_h);
    cudaGetSymbolAddress((void**)&pw1ll,  g_w1l_l);
    cudaGetSymbolAddress((void**)&pw1ch,  g_w1c_h);
    cudaGetSymbolAddress((void**)&pw1cl,  g_w1c_l);

    constexpr int SM64 = 2 * (2 * 64 * ROWP + 2 * TILB);   // 61440
    static bool attr_set = false;
    if (!attr_set) {
        cudaFuncSetAttribute(k_mma3<64, true>, cudaFuncAttributeMaxDynamicSharedMemorySize, SM64);
        cudaFuncSetAttribute(k_mmaf16, cudaFuncAttributeMaxDynamicSharedMemorySize, FSMEM);
        attr_set = true;
    }

    // 1) loc_W1 split
    k_wsplitT<<<dim3(HH / 32, SK / 32), dim3(32, 8)>>>(loc_W1, pw1ch, pw1cl, SK, HH);
    // 2) embed
    k_embed<<<RR, 64>>>(chars, emb);
    // 3) stack
    k_stack<<<dim3(RR, WW), 64>>>();
    // 4) loc hidden -> g_hb16 fp16   [PROFILED SLOT]
    k_mma3<64, true><<<dim3(RR / 64, HH / 128), 256, SM64>>>(
        psh, psl, pw1ch, pw1cl, loc_b1, phb, SK, HH);
    // 5) drive
    k_gemm<<<dim3(MM / GBN, RR / GBM), 256>>>(px, in_proj, pdrive, MM, EE);
    // 6) scan
    k_scan<<<2, 256>>>(decays);
    // 7) lin_W1 split
    k_wsplitT<<<dim3(HH / 32, ZK / 32), dim3(32, 8)>>>(lin_W1, pw1lh, pw1ll, ZK, HH);
    // 8) lin hidden -> g_ha16 fp16
    k_mma3<64, true><<<dim3(RR / 64, HH / 128), 256, SM64>>>(
        pzh, pzl, pw1lh, pw1ll, lin_b1, pha, ZK, HH);
    // 9) lin_W2 -> fp16 transposed
    k_wconvT<<<dim3(VV / 32, HH / 32), dim3(32, 8)>>>(lin_W2, pwl, HH, VV);
    // 10) lin logits (fp16 single product) -> d_out
    k_mmaf16<<<dim3(RR / 128, VV / 128), 256, FSMEM>>>(pha, pwl, lin_b2, out, HH, VV);
    // 11) loc_W2 -> fp16 transposed
    k_wconvT<<<dim3(VV / 32, HH / 32), dim3(32, 8)>>>(loc_W2, pwc, HH, VV);
    // 12) loc logits -> g_loc
    k_mmaf16<<<dim3(RR / 128, VV / 128), 256, FSMEM>>>(phb, pwc, loc_b2, ploc, HH, VV);
    // 13) fused gate + mix
    k_gatemix<<<RR, 256>>>(out, gate_W, gate_b);
}